// round 12
// baseline (speedup 1.0000x reference)
#include <cuda_runtime.h>
#include <cuda_fp16.h>
#include <math.h>
#include <stdint.h>

#define BB 2
#define SS 2048
#define DD 1024
#define HH 16
#define MM (BB*SS)

// Scratch (allocation-free rule: __device__ globals)
__device__ float g_Q[(size_t)MM * DD];
__device__ float g_K[(size_t)MM * DD];
__device__ float g_V[(size_t)MM * DD];
__device__ float g_ctx[(size_t)MM * DD];

// fp16 MMA: D(16x8,f32) += A(16x16,f16) @ B(16x8,f16)
__device__ __forceinline__ void mma16(float* d, const uint32_t* a, const uint32_t* b) {
    asm volatile(
        "mma.sync.aligned.m16n8k16.row.col.f32.f16.f16.f32 "
        "{%0,%1,%2,%3}, {%4,%5,%6,%7}, {%8,%9}, {%0,%1,%2,%3};\n"
        : "+f"(d[0]), "+f"(d[1]), "+f"(d[2]), "+f"(d[3])
        : "r"(a[0]), "r"(a[1]), "r"(a[2]), "r"(a[3]), "r"(b[0]), "r"(b[1]));
}
__device__ __forceinline__ uint32_t f22h(float lo, float hi) {
    __half2 h = __floats2half2_rn(lo, hi);   // .x = lo (low 16 bits)
    return *(uint32_t*)&h;
}

// ===========================================================================
// GEMM: C = A @ W + bias (fp16 mma.sync m16n8k16, fp32 accum).
// Block 128x128, BK=32, 256 threads = 8 warps as 2(M) x 4(N).
// A smem: [row][k-pairs] stride 20 words; B smem: [n][k-pairs] stride 20.
// Frag bank = (20g+tig)%32 -> conflict-free. Ping-pong, register prefetch,
// store-side convert (fp32->fp16 pack), 1 barrier/chunk.
// ===========================================================================
#define SA 20
#define SB 20
#define GA2 (128 * SA)                    // 2560 words per A stage
#define GB2 (128 * SB)                    // 2560 words per B stage
#define GEMM_SMEM ((2 * GA2 + 2 * GB2) * 4)   // 40960 B

__global__ void __launch_bounds__(256, 2) gemm_tc(
    const float* __restrict__ A0, const float* __restrict__ A1, const float* __restrict__ A2,
    const float* __restrict__ W0, const float* __restrict__ W1, const float* __restrict__ W2,
    const float* __restrict__ b0, const float* __restrict__ b1, const float* __restrict__ b2,
    float* __restrict__ C0, float* __restrict__ C1, float* __restrict__ C2)
{
    extern __shared__ uint32_t gsm[];
    const int z = blockIdx.z;
    const float* A = (z == 0) ? A0 : (z == 1) ? A1 : A2;
    const float* W = (z == 0) ? W0 : (z == 1) ? W1 : W2;
    const float* bias = (z == 0) ? b0 : (z == 1) ? b1 : b2;
    float* C = (z == 0) ? C0 : (z == 1) ? C1 : C2;

    const int tid  = threadIdx.x;
    const int lane = tid & 31, warp = tid >> 5;
    const int g = lane >> 2, tig = lane & 3;
    const int wm = warp >> 2, wn = warp & 3;
    const int row0 = blockIdx.y * 128, col0 = blockIdx.x * 128;

    // fill mappings
    const int rA = tid >> 1, khA = (tid & 1) * 16;   // A: row rA, halves khA..khA+15
    const int nB0 = lane * 4, kp0 = warp * 2;        // B: cols nB0..+3, k-pairs kp0,kp0+1
    const float* Ap = A + (size_t)(row0 + rA) * DD + khA;

    float acc[4][4][4] = {};
    float4 av[4], bv[4];

    auto loadB = [&](int k0, float4* dst) {
        #pragma unroll
        for (int i = 0; i < 2; i++) {
            const int kr = k0 + 2 * (kp0 + i);
            dst[2 * i]     = *(const float4*)(W + (size_t)kr * DD + col0 + nB0);
            dst[2 * i + 1] = *(const float4*)(W + (size_t)(kr + 1) * DD + col0 + nB0);
        }
    };
    auto storeStage = [&](int s) {
        uint32_t* As = gsm + s * GA2;
        uint32_t* Bs = gsm + 2 * GA2 + s * GB2;
        const float* af = (const float*)av;   // 16 consecutive floats
        #pragma unroll
        for (int i = 0; i < 2; i++) {
            uint4 t;
            t.x = f22h(af[8 * i + 0], af[8 * i + 1]);
            t.y = f22h(af[8 * i + 2], af[8 * i + 3]);
            t.z = f22h(af[8 * i + 4], af[8 * i + 5]);
            t.w = f22h(af[8 * i + 6], af[8 * i + 7]);
            *(uint4*)&As[rA * SA + khA / 2 + 4 * i] = t;
        }
        const float* b0f = (const float*)&bv[0];
        const float* b1f = (const float*)&bv[1];
        const float* b2f = (const float*)&bv[2];
        const float* b3f = (const float*)&bv[3];
        #pragma unroll
        for (int e = 0; e < 4; e++) {
            uint2 t;
            t.x = f22h(b0f[e], b1f[e]);      // k-pair kp0
            t.y = f22h(b2f[e], b3f[e]);      // k-pair kp0+1
            *(uint2*)&Bs[(nB0 + e) * SB + kp0] = t;
        }
    };

    // ---- prologue: chunk 0 -> stage 0 ----
    #pragma unroll
    for (int i = 0; i < 4; i++) av[i] = *(const float4*)(Ap + 4 * i);
    loadB(0, bv);
    storeStage(0);
    __syncthreads();

    for (int c = 0; c < 32; c++) {
        // prefetch next chunk into registers (hidden under MMA loop)
        if (c + 1 < 32) {
            const int k0 = (c + 1) * 32;
            #pragma unroll
            for (int i = 0; i < 4; i++)
                av[i] = *(const float4*)(Ap + k0 + 4 * i);
            loadB(k0, bv);
        }

        const uint32_t* As = gsm + (c & 1) * GA2;
        const uint32_t* Bs = gsm + 2 * GA2 + (c & 1) * GB2;

        #pragma unroll
        for (int k16 = 0; k16 < 2; k16++) {
            const int kb = k16 * 8;
            uint32_t af[4][4], bf[4][2];
            #pragma unroll
            for (int mt = 0; mt < 4; mt++) {
                const int r = wm * 64 + mt * 16 + g;
                af[mt][0] = As[r * SA + kb + tig];
                af[mt][1] = As[(r + 8) * SA + kb + tig];
                af[mt][2] = As[r * SA + kb + tig + 4];
                af[mt][3] = As[(r + 8) * SA + kb + tig + 4];
            }
            #pragma unroll
            for (int j = 0; j < 4; j++) {
                const int n = wn * 32 + j * 8 + g;
                bf[j][0] = Bs[n * SB + kb + tig];
                bf[j][1] = Bs[n * SB + kb + tig + 4];
            }
            #pragma unroll
            for (int mt = 0; mt < 4; mt++)
                #pragma unroll
                for (int j = 0; j < 4; j++)
                    mma16(acc[mt][j], af[mt], bf[j]);
        }

        // store next chunk into the other stage, then single barrier
        if (c + 1 < 32) {
            storeStage((c + 1) & 1);
            __syncthreads();
        }
    }

    // epilogue: bias + store
    #pragma unroll
    for (int mt = 0; mt < 4; mt++) {
        #pragma unroll
        for (int j = 0; j < 4; j++) {
            const int n = col0 + wn * 32 + j * 8 + 2 * tig;
            const float bb0 = bias[n], bb1 = bias[n + 1];
            const int r = row0 + wm * 64 + mt * 16 + g;
            *(float2*)&C[(size_t)r * DD + n] =
                make_float2(acc[mt][j][0] + bb0, acc[mt][j][1] + bb1);
            *(float2*)&C[(size_t)(r + 8) * DD + n] =
                make_float2(acc[mt][j][2] + bb0, acc[mt][j][3] + bb1);
        }
    }
}

// ===========================================================================
// Flash attention, fp16 mma.sync m16n8k16, fp32 accumulate.
// Byte-identical to the proven R11 kernel (~242us).
// ===========================================================================
#define RW 36                       // row stride in 4B words (72 halves)
#define KWD (64 * RW)
#define VOFF KWD
#define STG (2 * KWD)
#define ATTN_SMEM (2 * STG * 4)     // 36864 B
#define NT (SS / 64)

__global__ void __launch_bounds__(128) attn_tc()
{
    extern __shared__ uint32_t sm[];

    const int tid  = threadIdx.x;
    const int lane = tid & 31, warp = tid >> 5;
    const int g = lane >> 2, tig = lane & 3;
    const int wr0 = warp * 32;
    const int qt = blockIdx.x;
    const int b  = blockIdx.y >> 4;
    const int h  = blockIdx.y & 15;

    const float* Qg = g_Q + (size_t)(b * SS + qt * 128) * DD + h * 64;
    const float* Kg = g_K + (size_t)(b * SS) * DD + h * 64;
    const float* Vg = g_V + (size_t)(b * SS) * DD + h * 64;

    #pragma unroll
    for (int p = 0; p < 16; p++) {
        const int i = tid + 128 * p;
        const int r = i >> 4, c4 = (i & 15) * 4;
        float4 qv = *(const float4*)(Qg + (size_t)r * DD + c4);
        *(uint2*)&sm[STG + r * RW + c4 / 2] =
            make_uint2(f22h(qv.x * 0.125f, qv.y * 0.125f),
                       f22h(qv.z * 0.125f, qv.w * 0.125f));
    }
    __syncthreads();

    uint32_t qa[2][4][4];
    #pragma unroll
    for (int mt = 0; mt < 2; mt++) {
        const int r = wr0 + mt * 16 + g;
        #pragma unroll
        for (int k16 = 0; k16 < 4; k16++) {
            const int base = STG + r * RW + k16 * 8 + tig;
            qa[mt][k16][0] = sm[base];
            qa[mt][k16][1] = sm[base + 8 * RW];
            qa[mt][k16][2] = sm[base + 4];
            qa[mt][k16][3] = sm[base + 8 * RW + 4];
        }
    }

    {
        const float* Kt = Kg;
        const float* Vt = Vg;
        const int key = tid >> 1, dk0 = (tid & 1) * 32;
        #pragma unroll
        for (int i = 0; i < 8; i++) {
            float4 kf = *(const float4*)(Kt + (size_t)key * DD + dk0 + 4 * i);
            *(uint2*)&sm[key * RW + dk0 / 2 + 2 * i] =
                make_uint2(f22h(kf.x, kf.y), f22h(kf.z, kf.w));
        }
        const int pk = lane;
        #pragma unroll
        for (int p = 0; p < 4; p++) {
            const int d0 = (warp + 4 * p) * 4;
            float4 va = *(const float4*)(Vt + (size_t)(2 * pk) * DD + d0);
            float4 vb = *(const float4*)(Vt + (size_t)(2 * pk + 1) * DD + d0);
            const float* fa = (const float*)&va;
            const float* fb = (const float*)&vb;
            #pragma unroll
            for (int e = 0; e < 4; e++)
                sm[VOFF + (d0 + e) * RW + pk] = f22h(fa[e], fb[e]);
        }
    }
    __syncthreads();

    float of[2][8][4] = {};
    float mrow[2][2] = {{-1e30f, -1e30f}, {-1e30f, -1e30f}};
    float lrow[2][2] = {{0.f, 0.f}, {0.f, 0.f}};

    const int fkey = tid >> 1, fdk0 = (tid & 1) * 32;
    const int fpk = lane;

    for (int kt = 0; kt < NT; kt++) {
        const uint32_t* Ks  = sm + (kt & 1) * STG;
        const uint32_t* Vts = sm + (kt & 1) * STG + VOFF;

        float sf[2][8][4] = {};
        #pragma unroll
        for (int k16 = 0; k16 < 4; k16++) {
            uint32_t bf[8][2];
            #pragma unroll
            for (int j = 0; j < 8; j++) {
                const int w0 = (8 * j + g) * RW + 8 * k16 + tig;
                bf[j][0] = Ks[w0];
                bf[j][1] = Ks[w0 + 4];
            }
            #pragma unroll
            for (int mt = 0; mt < 2; mt++)
                #pragma unroll
                for (int j = 0; j < 8; j++)
                    mma16(sf[mt][j], qa[mt][k16], bf[j]);
        }

        #pragma unroll
        for (int mt = 0; mt < 2; mt++) {
            #pragma unroll
            for (int i = 0; i < 2; i++) {
                float mx = -1e30f;
                #pragma unroll
                for (int j = 0; j < 8; j++)
                    mx = fmaxf(mx, fmaxf(sf[mt][j][2 * i], sf[mt][j][2 * i + 1]));
                mx = fmaxf(mx, __shfl_xor_sync(0xffffffffu, mx, 1));
                mx = fmaxf(mx, __shfl_xor_sync(0xffffffffu, mx, 2));
                const float mn = fmaxf(mrow[mt][i], mx);
                const float corr = __expf(mrow[mt][i] - mn);
                mrow[mt][i] = mn;
                float rs = 0.f;
                #pragma unroll
                for (int j = 0; j < 8; j++) {
                    sf[mt][j][2 * i]     = __expf(sf[mt][j][2 * i] - mn);
                    sf[mt][j][2 * i + 1] = __expf(sf[mt][j][2 * i + 1] - mn);
                    rs += sf[mt][j][2 * i] + sf[mt][j][2 * i + 1];
                }
                rs += __shfl_xor_sync(0xffffffffu, rs, 1);
                rs += __shfl_xor_sync(0xffffffffu, rs, 2);
                lrow[mt][i] = lrow[mt][i] * corr + rs;
                #pragma unroll
                for (int j = 0; j < 8; j++) {
                    of[mt][j][2 * i]     *= corr;
                    of[mt][j][2 * i + 1] *= corr;
                }
            }
        }

        uint32_t pa[2][4][4];
        #pragma unroll
        for (int mt = 0; mt < 2; mt++)
            #pragma unroll
            for (int k16 = 0; k16 < 4; k16++) {
                pa[mt][k16][0] = f22h(sf[mt][2 * k16][0],     sf[mt][2 * k16][1]);
                pa[mt][k16][1] = f22h(sf[mt][2 * k16][2],     sf[mt][2 * k16][3]);
                pa[mt][k16][2] = f22h(sf[mt][2 * k16 + 1][0], sf[mt][2 * k16 + 1][1]);
                pa[mt][k16][3] = f22h(sf[mt][2 * k16 + 1][2], sf[mt][2 * k16 + 1][3]);
            }

        const bool more = (kt + 1 < NT);
        float4 kf[8], va[4], vb[4];
        if (more) {
            const float* Kt = Kg + (size_t)((kt + 1) * 64) * DD;
            const float* Vt = Vg + (size_t)((kt + 1) * 64) * DD;
            #pragma unroll
            for (int i = 0; i < 8; i++)
                kf[i] = *(const float4*)(Kt + (size_t)fkey * DD + fdk0 + 4 * i);
            #pragma unroll
            for (int p = 0; p < 4; p++) {
                const int d0 = (warp + 4 * p) * 4;
                va[p] = *(const float4*)(Vt + (size_t)(2 * fpk) * DD + d0);
                vb[p] = *(const float4*)(Vt + (size_t)(2 * fpk + 1) * DD + d0);
            }
        }

        #pragma unroll
        for (int k16 = 0; k16 < 4; k16++) {
            uint32_t bb[8][2];
            #pragma unroll
            for (int j = 0; j < 8; j++) {
                const int w0 = (8 * j + g) * RW + 8 * k16 + tig;
                bb[j][0] = Vts[w0];
                bb[j][1] = Vts[w0 + 4];
            }
            #pragma unroll
            for (int mt = 0; mt < 2; mt++)
                #pragma unroll
                for (int j = 0; j < 8; j++)
                    mma16(of[mt][j], pa[mt][k16], bb[j]);
        }

        if (more) {
            uint32_t* dst = sm + ((kt + 1) & 1) * STG;
            #pragma unroll
            for (int i = 0; i < 8; i++)
                *(uint2*)&dst[fkey * RW + fdk0 / 2 + 2 * i] =
                    make_uint2(f22h(kf[i].x, kf[i].y), f22h(kf[i].z, kf[i].w));
            #pragma unroll
            for (int p = 0; p < 4; p++) {
                const int d0 = (warp + 4 * p) * 4;
                const float* fa = (const float*)&va[p];
                const float* fb = (const float*)&vb[p];
                #pragma unroll
                for (int e = 0; e < 4; e++)
                    dst[VOFF + (d0 + e) * RW + fpk] = f22h(fa[e], fb[e]);
            }
        }
        __syncthreads();
    }

    #pragma unroll
    for (int mt = 0; mt < 2; mt++) {
        const float inv0 = 1.f / lrow[mt][0], inv1 = 1.f / lrow[mt][1];
        const size_t orow = (size_t)(b * SS + qt * 128 + wr0 + mt * 16 + g);
        #pragma unroll
        for (int j = 0; j < 8; j++) {
            const int n = h * 64 + j * 8 + 2 * tig;
            *(float2*)&g_ctx[orow * DD + n] =
                make_float2(of[mt][j][0] * inv0, of[mt][j][1] * inv0);
            *(float2*)&g_ctx[(orow + 8) * DD + n] =
                make_float2(of[mt][j][2] * inv1, of[mt][j][3] * inv1);
        }
    }
}

// ---------------------------------------------------------------------------
extern "C" void kernel_launch(void* const* d_in, const int* in_sizes, int n_in,
                              void* d_out, int out_size)
{
    (void)in_sizes; (void)n_in; (void)out_size;
    const float* q  = (const float*)d_in[0];
    const float* k  = (const float*)d_in[1];
    const float* v  = (const float*)d_in[2];
    const float* wq = (const float*)d_in[3];
    const float* bq = (const float*)d_in[4];
    const float* wk = (const float*)d_in[5];
    const float* bk = (const float*)d_in[6];
    const float* wv = (const float*)d_in[7];
    const float* bv = (const float*)d_in[8];
    const float* wo = (const float*)d_in[9];
    const float* bo = (const float*)d_in[10];
    float* out = (float*)d_out;

    float *gq, *gk, *gv, *gctx;
    cudaGetSymbolAddress((void**)&gq,   g_Q);
    cudaGetSymbolAddress((void**)&gk,   g_K);
    cudaGetSymbolAddress((void**)&gv,   g_V);
    cudaGetSymbolAddress((void**)&gctx, g_ctx);

    cudaFuncSetAttribute(gemm_tc, cudaFuncAttributeMaxDynamicSharedMemorySize, GEMM_SMEM);

    // fused Q/K/V projections: one launch, grid.z = 3
    gemm_tc<<<dim3(DD / 128, MM / 128, 3), 256, GEMM_SMEM>>>(
        q, k, v, wq, wk, wv, bq, bk, bv, gq, gk, gv);

    attn_tc<<<dim3(SS / 128, BB * HH), 128, ATTN_SMEM>>>();

    // output projection
    gemm_tc<<<dim3(DD / 128, MM / 128, 1), 256, GEMM_SMEM>>>(
        gctx, gctx, gctx, wo, wo, wo, bo, bo, bo, out, out, out);
}

// round 13
// speedup vs baseline: 1.0861x; 1.0861x over previous
#include <cuda_runtime.h>
#include <cuda_fp16.h>
#include <math.h>
#include <stdint.h>

#define BB 2
#define SS 2048
#define DD 1024
#define HH 16
#define MM (BB*SS)

// Scratch (allocation-free rule: __device__ globals)
__device__ float g_Q[(size_t)MM * DD];
__device__ float g_K[(size_t)MM * DD];
__device__ float g_V[(size_t)MM * DD];
__device__ float g_ctx[(size_t)MM * DD];

// fp16 MMA: D(16x8,f32) += A(16x16,f16) @ B(16x8,f16)
__device__ __forceinline__ void mma16(float* d, const uint32_t* a, const uint32_t* b) {
    asm volatile(
        "mma.sync.aligned.m16n8k16.row.col.f32.f16.f16.f32 "
        "{%0,%1,%2,%3}, {%4,%5,%6,%7}, {%8,%9}, {%0,%1,%2,%3};\n"
        : "+f"(d[0]), "+f"(d[1]), "+f"(d[2]), "+f"(d[3])
        : "r"(a[0]), "r"(a[1]), "r"(a[2]), "r"(a[3]), "r"(b[0]), "r"(b[1]));
}
__device__ __forceinline__ uint32_t f22h(float lo, float hi) {
    __half2 h = __floats2half2_rn(lo, hi);   // .x = lo (low 16 bits)
    return *(uint32_t*)&h;
}

// ===========================================================================
// GEMM: C = A @ W + bias (fp16 mma.sync m16n8k16, fp32 accum).
// Block 128x128, BK=32, 256 threads = 8 warps as 2(M) x 4(N).
// A smem: [row][k-pair] stride 20 words (frag bank 20g+tig distinct).
// B smem: [k-pair][n] stride 136 words (frag bank 8tig+g distinct; fill is
//   contiguous STS.128 from coalesced row loads -- the R12 16-way-conflict
//   fill store is gone).
// Ping-pong, register prefetch, store-side convert, 1 barrier/chunk.
// ===========================================================================
#define SA 20
#define SBW 136
#define GA2 (128 * SA)                    // 2560 words per A stage
#define GB2 (16 * SBW)                    // 2176 words per B stage
#define GEMM_SMEM ((2 * GA2 + 2 * GB2) * 4)   // 37888 B

__global__ void __launch_bounds__(256, 2) gemm_tc(
    const float* __restrict__ A0, const float* __restrict__ A1, const float* __restrict__ A2,
    const float* __restrict__ W0, const float* __restrict__ W1, const float* __restrict__ W2,
    const float* __restrict__ b0, const float* __restrict__ b1, const float* __restrict__ b2,
    float* __restrict__ C0, float* __restrict__ C1, float* __restrict__ C2)
{
    extern __shared__ uint32_t gsm[];
    const int z = blockIdx.z;
    const float* A = (z == 0) ? A0 : (z == 1) ? A1 : A2;
    const float* W = (z == 0) ? W0 : (z == 1) ? W1 : W2;
    const float* bias = (z == 0) ? b0 : (z == 1) ? b1 : b2;
    float* C = (z == 0) ? C0 : (z == 1) ? C1 : C2;

    const int tid  = threadIdx.x;
    const int lane = tid & 31, warp = tid >> 5;
    const int g = lane >> 2, tig = lane & 3;
    const int wm = warp >> 2, wn = warp & 3;
    const int row0 = blockIdx.y * 128, col0 = blockIdx.x * 128;

    // fill mappings
    const int rA = tid >> 1, khA = (tid & 1) * 16;   // A: row rA, halves khA..+15
    const int pB = tid >> 4, nB0 = (tid & 15) * 8;   // B: k-pair row pB, cols nB0..+7
    const float* Ap = A + (size_t)(row0 + rA) * DD + khA;
    const float* Wp0 = W + (size_t)(2 * pB) * DD + col0 + nB0;       // even k row
    const float* Wp1 = W + (size_t)(2 * pB + 1) * DD + col0 + nB0;   // odd k row

    float acc[4][4][4] = {};
    float4 av[4], bv[4];

    auto loadAB = [&](int k0) {
        #pragma unroll
        for (int i = 0; i < 4; i++) av[i] = *(const float4*)(Ap + k0 + 4 * i);
        bv[0] = *(const float4*)(Wp0 + (size_t)k0 * DD);
        bv[1] = *(const float4*)(Wp0 + (size_t)k0 * DD + 4);
        bv[2] = *(const float4*)(Wp1 + (size_t)k0 * DD);
        bv[3] = *(const float4*)(Wp1 + (size_t)k0 * DD + 4);
    };
    auto storeStage = [&](int s) {
        uint32_t* As = gsm + s * GA2;
        uint32_t* Bs = gsm + 2 * GA2 + s * GB2;
        const float* af = (const float*)av;   // 16 consecutive floats
        #pragma unroll
        for (int i = 0; i < 2; i++) {
            uint4 t;
            t.x = f22h(af[8 * i + 0], af[8 * i + 1]);
            t.y = f22h(af[8 * i + 2], af[8 * i + 3]);
            t.z = f22h(af[8 * i + 4], af[8 * i + 5]);
            t.w = f22h(af[8 * i + 6], af[8 * i + 7]);
            *(uint4*)&As[rA * SA + khA / 2 + 4 * i] = t;
        }
        const float* e0 = (const float*)&bv[0];   // even row, cols n0..n0+3
        const float* e1 = (const float*)&bv[1];   // even row, cols n0+4..n0+7
        const float* o0 = (const float*)&bv[2];   // odd row
        const float* o1 = (const float*)&bv[3];
        uint4 t0, t1;
        t0.x = f22h(e0[0], o0[0]); t0.y = f22h(e0[1], o0[1]);
        t0.z = f22h(e0[2], o0[2]); t0.w = f22h(e0[3], o0[3]);
        t1.x = f22h(e1[0], o1[0]); t1.y = f22h(e1[1], o1[1]);
        t1.z = f22h(e1[2], o1[2]); t1.w = f22h(e1[3], o1[3]);
        *(uint4*)&Bs[pB * SBW + nB0]     = t0;
        *(uint4*)&Bs[pB * SBW + nB0 + 4] = t1;
    };

    // ---- prologue: chunk 0 -> stage 0 ----
    loadAB(0);
    storeStage(0);
    __syncthreads();

    for (int c = 0; c < 32; c++) {
        // prefetch next chunk into registers (hidden under MMA loop)
        if (c + 1 < 32) loadAB((c + 1) * 32);

        const uint32_t* As = gsm + (c & 1) * GA2;
        const uint32_t* Bs = gsm + 2 * GA2 + (c & 1) * GB2;

        #pragma unroll
        for (int k16 = 0; k16 < 2; k16++) {
            uint32_t af[4][4], bf[4][2];
            #pragma unroll
            for (int mt = 0; mt < 4; mt++) {
                const int r = wm * 64 + mt * 16 + g;
                af[mt][0] = As[r * SA + k16 * 8 + tig];
                af[mt][1] = As[(r + 8) * SA + k16 * 8 + tig];
                af[mt][2] = As[r * SA + k16 * 8 + tig + 4];
                af[mt][3] = As[(r + 8) * SA + k16 * 8 + tig + 4];
            }
            #pragma unroll
            for (int j = 0; j < 4; j++) {
                const int n = wn * 32 + j * 8 + g;
                bf[j][0] = Bs[(k16 * 8 + tig) * SBW + n];
                bf[j][1] = Bs[(k16 * 8 + tig + 4) * SBW + n];
            }
            #pragma unroll
            for (int mt = 0; mt < 4; mt++)
                #pragma unroll
                for (int j = 0; j < 4; j++)
                    mma16(acc[mt][j], af[mt], bf[j]);
        }

        // store next chunk into the other stage, then single barrier
        if (c + 1 < 32) {
            storeStage((c + 1) & 1);
            __syncthreads();
        }
    }

    // epilogue: bias + store
    #pragma unroll
    for (int mt = 0; mt < 4; mt++) {
        #pragma unroll
        for (int j = 0; j < 4; j++) {
            const int n = col0 + wn * 32 + j * 8 + 2 * tig;
            const float bb0 = bias[n], bb1 = bias[n + 1];
            const int r = row0 + wm * 64 + mt * 16 + g;
            *(float2*)&C[(size_t)r * DD + n] =
                make_float2(acc[mt][j][0] + bb0, acc[mt][j][1] + bb1);
            *(float2*)&C[(size_t)(r + 8) * DD + n] =
                make_float2(acc[mt][j][2] + bb0, acc[mt][j][3] + bb1);
        }
    }
}

// ===========================================================================
// Flash attention, fp16 mma.sync m16n8k16, fp32 accumulate.
// Byte-identical to the proven R11 kernel (~242us).
// ===========================================================================
#define RW 36                       // row stride in 4B words (72 halves)
#define KWD (64 * RW)
#define VOFF KWD
#define STG (2 * KWD)
#define ATTN_SMEM (2 * STG * 4)     // 36864 B
#define NT (SS / 64)

__global__ void __launch_bounds__(128) attn_tc()
{
    extern __shared__ uint32_t sm[];

    const int tid  = threadIdx.x;
    const int lane = tid & 31, warp = tid >> 5;
    const int g = lane >> 2, tig = lane & 3;
    const int wr0 = warp * 32;
    const int qt = blockIdx.x;
    const int b  = blockIdx.y >> 4;
    const int h  = blockIdx.y & 15;

    const float* Qg = g_Q + (size_t)(b * SS + qt * 128) * DD + h * 64;
    const float* Kg = g_K + (size_t)(b * SS) * DD + h * 64;
    const float* Vg = g_V + (size_t)(b * SS) * DD + h * 64;

    #pragma unroll
    for (int p = 0; p < 16; p++) {
        const int i = tid + 128 * p;
        const int r = i >> 4, c4 = (i & 15) * 4;
        float4 qv = *(const float4*)(Qg + (size_t)r * DD + c4);
        *(uint2*)&sm[STG + r * RW + c4 / 2] =
            make_uint2(f22h(qv.x * 0.125f, qv.y * 0.125f),
                       f22h(qv.z * 0.125f, qv.w * 0.125f));
    }
    __syncthreads();

    uint32_t qa[2][4][4];
    #pragma unroll
    for (int mt = 0; mt < 2; mt++) {
        const int r = wr0 + mt * 16 + g;
        #pragma unroll
        for (int k16 = 0; k16 < 4; k16++) {
            const int base = STG + r * RW + k16 * 8 + tig;
            qa[mt][k16][0] = sm[base];
            qa[mt][k16][1] = sm[base + 8 * RW];
            qa[mt][k16][2] = sm[base + 4];
            qa[mt][k16][3] = sm[base + 8 * RW + 4];
        }
    }

    {
        const float* Kt = Kg;
        const float* Vt = Vg;
        const int key = tid >> 1, dk0 = (tid & 1) * 32;
        #pragma unroll
        for (int i = 0; i < 8; i++) {
            float4 kf = *(const float4*)(Kt + (size_t)key * DD + dk0 + 4 * i);
            *(uint2*)&sm[key * RW + dk0 / 2 + 2 * i] =
                make_uint2(f22h(kf.x, kf.y), f22h(kf.z, kf.w));
        }
        const int pk = lane;
        #pragma unroll
        for (int p = 0; p < 4; p++) {
            const int d0 = (warp + 4 * p) * 4;
            float4 va = *(const float4*)(Vt + (size_t)(2 * pk) * DD + d0);
            float4 vb = *(const float4*)(Vt + (size_t)(2 * pk + 1) * DD + d0);
            const float* fa = (const float*)&va;
            const float* fb = (const float*)&vb;
            #pragma unroll
            for (int e = 0; e < 4; e++)
                sm[VOFF + (d0 + e) * RW + pk] = f22h(fa[e], fb[e]);
        }
    }
    __syncthreads();

    float of[2][8][4] = {};
    float mrow[2][2] = {{-1e30f, -1e30f}, {-1e30f, -1e30f}};
    float lrow[2][2] = {{0.f, 0.f}, {0.f, 0.f}};

    const int fkey = tid >> 1, fdk0 = (tid & 1) * 32;
    const int fpk = lane;

    for (int kt = 0; kt < NT; kt++) {
        const uint32_t* Ks  = sm + (kt & 1) * STG;
        const uint32_t* Vts = sm + (kt & 1) * STG + VOFF;

        float sf[2][8][4] = {};
        #pragma unroll
        for (int k16 = 0; k16 < 4; k16++) {
            uint32_t bf[8][2];
            #pragma unroll
            for (int j = 0; j < 8; j++) {
                const int w0 = (8 * j + g) * RW + 8 * k16 + tig;
                bf[j][0] = Ks[w0];
                bf[j][1] = Ks[w0 + 4];
            }
            #pragma unroll
            for (int mt = 0; mt < 2; mt++)
                #pragma unroll
                for (int j = 0; j < 8; j++)
                    mma16(sf[mt][j], qa[mt][k16], bf[j]);
        }

        #pragma unroll
        for (int mt = 0; mt < 2; mt++) {
            #pragma unroll
            for (int i = 0; i < 2; i++) {
                float mx = -1e30f;
                #pragma unroll
                for (int j = 0; j < 8; j++)
                    mx = fmaxf(mx, fmaxf(sf[mt][j][2 * i], sf[mt][j][2 * i + 1]));
                mx = fmaxf(mx, __shfl_xor_sync(0xffffffffu, mx, 1));
                mx = fmaxf(mx, __shfl_xor_sync(0xffffffffu, mx, 2));
                const float mn = fmaxf(mrow[mt][i], mx);
                const float corr = __expf(mrow[mt][i] - mn);
                mrow[mt][i] = mn;
                float rs = 0.f;
                #pragma unroll
                for (int j = 0; j < 8; j++) {
                    sf[mt][j][2 * i]     = __expf(sf[mt][j][2 * i] - mn);
                    sf[mt][j][2 * i + 1] = __expf(sf[mt][j][2 * i + 1] - mn);
                    rs += sf[mt][j][2 * i] + sf[mt][j][2 * i + 1];
                }
                rs += __shfl_xor_sync(0xffffffffu, rs, 1);
                rs += __shfl_xor_sync(0xffffffffu, rs, 2);
                lrow[mt][i] = lrow[mt][i] * corr + rs;
                #pragma unroll
                for (int j = 0; j < 8; j++) {
                    of[mt][j][2 * i]     *= corr;
                    of[mt][j][2 * i + 1] *= corr;
                }
            }
        }

        uint32_t pa[2][4][4];
        #pragma unroll
        for (int mt = 0; mt < 2; mt++)
            #pragma unroll
            for (int k16 = 0; k16 < 4; k16++) {
                pa[mt][k16][0] = f22h(sf[mt][2 * k16][0],     sf[mt][2 * k16][1]);
                pa[mt][k16][1] = f22h(sf[mt][2 * k16][2],     sf[mt][2 * k16][3]);
                pa[mt][k16][2] = f22h(sf[mt][2 * k16 + 1][0], sf[mt][2 * k16 + 1][1]);
                pa[mt][k16][3] = f22h(sf[mt][2 * k16 + 1][2], sf[mt][2 * k16 + 1][3]);
            }

        const bool more = (kt + 1 < NT);
        float4 kf[8], va[4], vb[4];
        if (more) {
            const float* Kt = Kg + (size_t)((kt + 1) * 64) * DD;
            const float* Vt = Vg + (size_t)((kt + 1) * 64) * DD;
            #pragma unroll
            for (int i = 0; i < 8; i++)
                kf[i] = *(const float4*)(Kt + (size_t)fkey * DD + fdk0 + 4 * i);
            #pragma unroll
            for (int p = 0; p < 4; p++) {
                const int d0 = (warp + 4 * p) * 4;
                va[p] = *(const float4*)(Vt + (size_t)(2 * fpk) * DD + d0);
                vb[p] = *(const float4*)(Vt + (size_t)(2 * fpk + 1) * DD + d0);
            }
        }

        #pragma unroll
        for (int k16 = 0; k16 < 4; k16++) {
            uint32_t bb[8][2];
            #pragma unroll
            for (int j = 0; j < 8; j++) {
                const int w0 = (8 * j + g) * RW + 8 * k16 + tig;
                bb[j][0] = Vts[w0];
                bb[j][1] = Vts[w0 + 4];
            }
            #pragma unroll
            for (int mt = 0; mt < 2; mt++)
                #pragma unroll
                for (int j = 0; j < 8; j++)
                    mma16(of[mt][j], pa[mt][k16], bb[j]);
        }

        if (more) {
            uint32_t* dst = sm + ((kt + 1) & 1) * STG;
            #pragma unroll
            for (int i = 0; i < 8; i++)
                *(uint2*)&dst[fkey * RW + fdk0 / 2 + 2 * i] =
                    make_uint2(f22h(kf[i].x, kf[i].y), f22h(kf[i].z, kf[i].w));
            #pragma unroll
            for (int p = 0; p < 4; p++) {
                const int d0 = (warp + 4 * p) * 4;
                const float* fa = (const float*)&va[p];
                const float* fb = (const float*)&vb[p];
                #pragma unroll
                for (int e = 0; e < 4; e++)
                    dst[VOFF + (d0 + e) * RW + fpk] = f22h(fa[e], fb[e]);
            }
        }
        __syncthreads();
    }

    #pragma unroll
    for (int mt = 0; mt < 2; mt++) {
        const float inv0 = 1.f / lrow[mt][0], inv1 = 1.f / lrow[mt][1];
        const size_t orow = (size_t)(b * SS + qt * 128 + wr0 + mt * 16 + g);
        #pragma unroll
        for (int j = 0; j < 8; j++) {
            const int n = h * 64 + j * 8 + 2 * tig;
            *(float2*)&g_ctx[orow * DD + n] =
                make_float2(of[mt][j][0] * inv0, of[mt][j][1] * inv0);
            *(float2*)&g_ctx[(orow + 8) * DD + n] =
                make_float2(of[mt][j][2] * inv1, of[mt][j][3] * inv1);
        }
    }
}

// ---------------------------------------------------------------------------
extern "C" void kernel_launch(void* const* d_in, const int* in_sizes, int n_in,
                              void* d_out, int out_size)
{
    (void)in_sizes; (void)n_in; (void)out_size;
    const float* q  = (const float*)d_in[0];
    const float* k  = (const float*)d_in[1];
    const float* v  = (const float*)d_in[2];
    const float* wq = (const float*)d_in[3];
    const float* bq = (const float*)d_in[4];
    const float* wk = (const float*)d_in[5];
    const float* bk = (const float*)d_in[6];
    const float* wv = (const float*)d_in[7];
    const float* bv = (const float*)d_in[8];
    const float* wo = (const float*)d_in[9];
    const float* bo = (const float*)d_in[10];
    float* out = (float*)d_out;

    float *gq, *gk, *gv, *gctx;
    cudaGetSymbolAddress((void**)&gq,   g_Q);
    cudaGetSymbolAddress((void**)&gk,   g_K);
    cudaGetSymbolAddress((void**)&gv,   g_V);
    cudaGetSymbolAddress((void**)&gctx, g_ctx);

    cudaFuncSetAttribute(gemm_tc, cudaFuncAttributeMaxDynamicSharedMemorySize, GEMM_SMEM);

    // fused Q/K/V projections: one launch, grid.z = 3
    gemm_tc<<<dim3(DD / 128, MM / 128, 3), 256, GEMM_SMEM>>>(
        q, k, v, wq, wk, wv, bq, bk, bv, gq, gk, gv);

    attn_tc<<<dim3(SS / 128, BB * HH), 128, ATTN_SMEM>>>();

    // output projection
    gemm_tc<<<dim3(DD / 128, MM / 128, 1), 256, GEMM_SMEM>>>(
        gctx, gctx, gctx, wo, wo, wo, bo, bo, bo, out, out, out);
}

// round 14
// speedup vs baseline: 1.6579x; 1.5265x over previous
#include <cuda_runtime.h>
#include <cuda_fp16.h>
#include <math.h>
#include <stdint.h>

#define BB 2
#define SS 2048
#define DD 1024
#define HH 16
#define MM (BB*SS)

// Scratch (allocation-free rule: __device__ globals)
__device__ float g_Q[(size_t)MM * DD];
__device__ float g_K[(size_t)MM * DD];
__device__ float g_V[(size_t)MM * DD];
__device__ float g_ctx[(size_t)MM * DD];

// fp16 MMA: D(16x8,f32) += A(16x16,f16) @ B(16x8,f16)
__device__ __forceinline__ void mma16(float* d, const uint32_t* a, const uint32_t* b) {
    asm volatile(
        "mma.sync.aligned.m16n8k16.row.col.f32.f16.f16.f32 "
        "{%0,%1,%2,%3}, {%4,%5,%6,%7}, {%8,%9}, {%0,%1,%2,%3};\n"
        : "+f"(d[0]), "+f"(d[1]), "+f"(d[2]), "+f"(d[3])
        : "r"(a[0]), "r"(a[1]), "r"(a[2]), "r"(a[3]), "r"(b[0]), "r"(b[1]));
}
__device__ __forceinline__ uint32_t f22h(float lo, float hi) {
    __half2 h = __floats2half2_rn(lo, hi);   // .x = lo (low 16 bits)
    return *(uint32_t*)&h;
}

// ===========================================================================
// GEMM: C = A @ W + bias (fp16 mma.sync m16n8k16, fp32 accum).
// Block 128x128, BK=32, 256 threads = 8 warps as 2(M) x 4(N).
// A smem [row][k-pair] stride 20; B smem [k-pair][n] stride 136 (unchanged
// fragment layouts). FILLS RE-COALESCED:
//   A: 8 lanes/row (4 lines per LDG.128), STS.64 stores.
//   B: warp loads full k-rows in pairs (4 lines per LDG.128), STS.128 stores.
// Ping-pong, register prefetch, store-side convert, 1 barrier/chunk.
// ===========================================================================
#define SA 20
#define SBW 136
#define GA2 (128 * SA)                    // 2560 words per A stage
#define GB2 (16 * SBW)                    // 2176 words per B stage
#define GEMM_SMEM ((2 * GA2 + 2 * GB2) * 4)   // 37888 B

__global__ void __launch_bounds__(256, 2) gemm_tc(
    const float* __restrict__ A0, const float* __restrict__ A1, const float* __restrict__ A2,
    const float* __restrict__ W0, const float* __restrict__ W1, const float* __restrict__ W2,
    const float* __restrict__ b0, const float* __restrict__ b1, const float* __restrict__ b2,
    float* __restrict__ C0, float* __restrict__ C1, float* __restrict__ C2)
{
    extern __shared__ uint32_t gsm[];
    const int z = blockIdx.z;
    const float* A = (z == 0) ? A0 : (z == 1) ? A1 : A2;
    const float* W = (z == 0) ? W0 : (z == 1) ? W1 : W2;
    const float* bias = (z == 0) ? b0 : (z == 1) ? b1 : b2;
    float* C = (z == 0) ? C0 : (z == 1) ? C1 : C2;

    const int tid  = threadIdx.x;
    const int lane = tid & 31, warp = tid >> 5;
    const int g = lane >> 2, tig = lane & 3;
    const int wm = warp >> 2, wn = warp & 3;
    const int row0 = blockIdx.y * 128, col0 = blockIdx.x * 128;

    // fill mappings (coalesced)
    const int rA = tid >> 3, cA = (tid & 7) * 4;   // A: 8 lanes/row, rows rA+32i
    const float* Ap = A + (size_t)(row0 + rA) * DD + cA;
    const float* WpB = W + (size_t)(2 * warp) * DD + col0 + 4 * lane;   // B row pairs

    float acc[4][4][4] = {};
    float4 av[4], bv[4];

    auto loadAB = [&](int k0) {
        #pragma unroll
        for (int i = 0; i < 4; i++)
            av[i] = *(const float4*)(Ap + k0 + (size_t)(32 * i) * DD);
        bv[0] = *(const float4*)(WpB + (size_t)k0 * DD);                 // row 2w
        bv[1] = *(const float4*)(WpB + (size_t)(k0 + 1) * DD);           // row 2w+1
        bv[2] = *(const float4*)(WpB + (size_t)(k0 + 16) * DD);          // row 2w+16
        bv[3] = *(const float4*)(WpB + (size_t)(k0 + 17) * DD);          // row 2w+17
    };
    auto storeStage = [&](int s) {
        uint32_t* As = gsm + s * GA2;
        uint32_t* Bs = gsm + 2 * GA2 + s * GB2;
        #pragma unroll
        for (int i = 0; i < 4; i++) {
            uint2 t;
            t.x = f22h(av[i].x, av[i].y);
            t.y = f22h(av[i].z, av[i].w);
            *(uint2*)&As[(rA + 32 * i) * SA + cA / 2] = t;
        }
        const float* e0 = (const float*)&bv[0];
        const float* o0 = (const float*)&bv[1];
        const float* e1 = (const float*)&bv[2];
        const float* o1 = (const float*)&bv[3];
        uint4 t0, t1;
        t0.x = f22h(e0[0], o0[0]); t0.y = f22h(e0[1], o0[1]);
        t0.z = f22h(e0[2], o0[2]); t0.w = f22h(e0[3], o0[3]);
        t1.x = f22h(e1[0], o1[0]); t1.y = f22h(e1[1], o1[1]);
        t1.z = f22h(e1[2], o1[2]); t1.w = f22h(e1[3], o1[3]);
        *(uint4*)&Bs[warp * SBW + 4 * lane]       = t0;   // k-pair warp
        *(uint4*)&Bs[(warp + 8) * SBW + 4 * lane] = t1;   // k-pair warp+8
    };

    // ---- prologue: chunk 0 -> stage 0 ----
    loadAB(0);
    storeStage(0);
    __syncthreads();

    for (int c = 0; c < 32; c++) {
        if (c + 1 < 32) loadAB((c + 1) * 32);

        const uint32_t* As = gsm + (c & 1) * GA2;
        const uint32_t* Bs = gsm + 2 * GA2 + (c & 1) * GB2;

        #pragma unroll
        for (int k16 = 0; k16 < 2; k16++) {
            uint32_t af[4][4], bf[4][2];
            #pragma unroll
            for (int mt = 0; mt < 4; mt++) {
                const int r = wm * 64 + mt * 16 + g;
                af[mt][0] = As[r * SA + k16 * 8 + tig];
                af[mt][1] = As[(r + 8) * SA + k16 * 8 + tig];
                af[mt][2] = As[r * SA + k16 * 8 + tig + 4];
                af[mt][3] = As[(r + 8) * SA + k16 * 8 + tig + 4];
            }
            #pragma unroll
            for (int j = 0; j < 4; j++) {
                const int n = wn * 32 + j * 8 + g;
                bf[j][0] = Bs[(k16 * 8 + tig) * SBW + n];
                bf[j][1] = Bs[(k16 * 8 + tig + 4) * SBW + n];
            }
            #pragma unroll
            for (int mt = 0; mt < 4; mt++)
                #pragma unroll
                for (int j = 0; j < 4; j++)
                    mma16(acc[mt][j], af[mt], bf[j]);
        }

        if (c + 1 < 32) {
            storeStage((c + 1) & 1);
            __syncthreads();
        }
    }

    // epilogue: bias + store
    #pragma unroll
    for (int mt = 0; mt < 4; mt++) {
        #pragma unroll
        for (int j = 0; j < 4; j++) {
            const int n = col0 + wn * 32 + j * 8 + 2 * tig;
            const float bb0 = bias[n], bb1 = bias[n + 1];
            const int r = row0 + wm * 64 + mt * 16 + g;
            *(float2*)&C[(size_t)r * DD + n] =
                make_float2(acc[mt][j][0] + bb0, acc[mt][j][1] + bb1);
            *(float2*)&C[(size_t)(r + 8) * DD + n] =
                make_float2(acc[mt][j][2] + bb0, acc[mt][j][3] + bb1);
        }
    }
}

// ===========================================================================
// Flash attention, fp16 mma.sync m16n8k16, fp32 accumulate.
// Same fragment pipeline as the proven R11 kernel; fills re-coalesced:
//   K fill: 16 lanes/row loads (4 lines/LDG), conflict-free STS.64.
//   V fill: row-PAIR loads (4 lines/LDG); V stride 36->37 so transposed
//           STS.32 banks (5*dk+rp) and V-frag banks are worst-case 2-way.
// ===========================================================================
#define RW 36                       // K/Q row stride in 4B words (72 halves)
#define VST 37                      // V row stride in words
#define KWD (64 * RW)               // 2304 words per K tile
#define VWD (64 * VST)              // 2368 words per V tile
#define VOFF KWD
#define STG (KWD + VWD)             // 4672 words per stage
#define ATTN_SMEM (2 * STG * 4)     // 37376 B
#define NT (SS / 64)

__global__ void __launch_bounds__(128) attn_tc()
{
    extern __shared__ uint32_t sm[];

    const int tid  = threadIdx.x;
    const int lane = tid & 31, warp = tid >> 5;
    const int g = lane >> 2, tig = lane & 3;
    const int wr0 = warp * 32;
    const int qt = blockIdx.x;
    const int b  = blockIdx.y >> 4;
    const int h  = blockIdx.y & 15;

    const float* Qg = g_Q + (size_t)(b * SS + qt * 128) * DD + h * 64;
    const float* Kg = g_K + (size_t)(b * SS) * DD + h * 64;
    const float* Vg = g_V + (size_t)(b * SS) * DD + h * 64;

    // fill mappings (coalesced)
    const int kr = tid >> 4, kc4 = (tid & 15) * 4;   // K: rows kr+8i, 16 lanes/row
    const int vrp = tid >> 3, vds = (tid & 7) * 8;   // V: row-pairs vrp+16*i2

    // ---- prologue: stage Q (scaled, fp16) into stage-1 K region ----
    #pragma unroll
    for (int p = 0; p < 16; p++) {
        const int i = tid + 128 * p;
        const int r = i >> 4, c4 = (i & 15) * 4;
        float4 qv = *(const float4*)(Qg + (size_t)r * DD + c4);
        *(uint2*)&sm[STG + r * RW + c4 / 2] =
            make_uint2(f22h(qv.x * 0.125f, qv.y * 0.125f),
                       f22h(qv.z * 0.125f, qv.w * 0.125f));
    }
    __syncthreads();

    // ---- extract persistent Q A-fragments ----
    uint32_t qa[2][4][4];
    #pragma unroll
    for (int mt = 0; mt < 2; mt++) {
        const int r = wr0 + mt * 16 + g;
        #pragma unroll
        for (int k16 = 0; k16 < 4; k16++) {
            const int base = STG + r * RW + k16 * 8 + tig;
            qa[mt][k16][0] = sm[base];
            qa[mt][k16][1] = sm[base + 8 * RW];
            qa[mt][k16][2] = sm[base + 4];
            qa[mt][k16][3] = sm[base + 8 * RW + 4];
        }
    }
    __syncthreads();   // all Q reads done before tile-1 fill reuses stage 1

    // ---- fill tile 0 into stage 0 (coalesced mappings) ----
    {
        #pragma unroll
        for (int i = 0; i < 8; i++) {
            float4 kf = *(const float4*)(Kg + (size_t)(kr + 8 * i) * DD + kc4);
            *(uint2*)&sm[(kr + 8 * i) * RW + kc4 / 2] =
                make_uint2(f22h(kf.x, kf.y), f22h(kf.z, kf.w));
        }
        #pragma unroll
        for (int i2 = 0; i2 < 2; i2++) {
            const int rp = vrp + 16 * i2;
            float4 a0 = *(const float4*)(Vg + (size_t)(2 * rp) * DD + vds);
            float4 a1 = *(const float4*)(Vg + (size_t)(2 * rp) * DD + vds + 4);
            float4 c0 = *(const float4*)(Vg + (size_t)(2 * rp + 1) * DD + vds);
            float4 c1 = *(const float4*)(Vg + (size_t)(2 * rp + 1) * DD + vds + 4);
            const float* fa = (const float*)&a0;   // a0,a1 contiguous? use both
            const float* fa1 = (const float*)&a1;
            const float* fb = (const float*)&c0;
            const float* fb1 = (const float*)&c1;
            #pragma unroll
            for (int e = 0; e < 4; e++) {
                sm[VOFF + (vds + e) * VST + rp]     = f22h(fa[e],  fb[e]);
                sm[VOFF + (vds + e + 4) * VST + rp] = f22h(fa1[e], fb1[e]);
            }
        }
    }
    __syncthreads();

    float of[2][8][4] = {};
    float mrow[2][2] = {{-1e30f, -1e30f}, {-1e30f, -1e30f}};
    float lrow[2][2] = {{0.f, 0.f}, {0.f, 0.f}};

    for (int kt = 0; kt < NT; kt++) {
        const uint32_t* Ks  = sm + (kt & 1) * STG;
        const uint32_t* Vts = sm + (kt & 1) * STG + VOFF;

        // ---- S = Qs @ K^T ----
        float sf[2][8][4] = {};
        #pragma unroll
        for (int k16 = 0; k16 < 4; k16++) {
            uint32_t bf[8][2];
            #pragma unroll
            for (int j = 0; j < 8; j++) {
                const int w0 = (8 * j + g) * RW + 8 * k16 + tig;
                bf[j][0] = Ks[w0];
                bf[j][1] = Ks[w0 + 4];
            }
            #pragma unroll
            for (int mt = 0; mt < 2; mt++)
                #pragma unroll
                for (int j = 0; j < 8; j++)
                    mma16(sf[mt][j], qa[mt][k16], bf[j]);
        }

        // ---- online softmax ----
        #pragma unroll
        for (int mt = 0; mt < 2; mt++) {
            #pragma unroll
            for (int i = 0; i < 2; i++) {
                float mx = -1e30f;
                #pragma unroll
                for (int j = 0; j < 8; j++)
                    mx = fmaxf(mx, fmaxf(sf[mt][j][2 * i], sf[mt][j][2 * i + 1]));
                mx = fmaxf(mx, __shfl_xor_sync(0xffffffffu, mx, 1));
                mx = fmaxf(mx, __shfl_xor_sync(0xffffffffu, mx, 2));
                const float mn = fmaxf(mrow[mt][i], mx);
                const float corr = __expf(mrow[mt][i] - mn);
                mrow[mt][i] = mn;
                float rs = 0.f;
                #pragma unroll
                for (int j = 0; j < 8; j++) {
                    sf[mt][j][2 * i]     = __expf(sf[mt][j][2 * i] - mn);
                    sf[mt][j][2 * i + 1] = __expf(sf[mt][j][2 * i + 1] - mn);
                    rs += sf[mt][j][2 * i] + sf[mt][j][2 * i + 1];
                }
                rs += __shfl_xor_sync(0xffffffffu, rs, 1);
                rs += __shfl_xor_sync(0xffffffffu, rs, 2);
                lrow[mt][i] = lrow[mt][i] * corr + rs;
                #pragma unroll
                for (int j = 0; j < 8; j++) {
                    of[mt][j][2 * i]     *= corr;
                    of[mt][j][2 * i + 1] *= corr;
                }
            }
        }

        // ---- pack P into PV A-fragments (registers only) ----
        uint32_t pa[2][4][4];
        #pragma unroll
        for (int mt = 0; mt < 2; mt++)
            #pragma unroll
            for (int k16 = 0; k16 < 4; k16++) {
                pa[mt][k16][0] = f22h(sf[mt][2 * k16][0],     sf[mt][2 * k16][1]);
                pa[mt][k16][1] = f22h(sf[mt][2 * k16][2],     sf[mt][2 * k16][3]);
                pa[mt][k16][2] = f22h(sf[mt][2 * k16 + 1][0], sf[mt][2 * k16 + 1][1]);
                pa[mt][k16][3] = f22h(sf[mt][2 * k16 + 1][2], sf[mt][2 * k16 + 1][3]);
            }

        // ---- issue next tile's global loads (hidden under PV) ----
        const bool more = (kt + 1 < NT);
        float4 kf[8], va0[2], va1[2], vb0[2], vb1[2];
        if (more) {
            const float* Kt = Kg + (size_t)((kt + 1) * 64) * DD;
            const float* Vt = Vg + (size_t)((kt + 1) * 64) * DD;
            #pragma unroll
            for (int i = 0; i < 8; i++)
                kf[i] = *(const float4*)(Kt + (size_t)(kr + 8 * i) * DD + kc4);
            #pragma unroll
            for (int i2 = 0; i2 < 2; i2++) {
                const int rp = vrp + 16 * i2;
                va0[i2] = *(const float4*)(Vt + (size_t)(2 * rp) * DD + vds);
                va1[i2] = *(const float4*)(Vt + (size_t)(2 * rp) * DD + vds + 4);
                vb0[i2] = *(const float4*)(Vt + (size_t)(2 * rp + 1) * DD + vds);
                vb1[i2] = *(const float4*)(Vt + (size_t)(2 * rp + 1) * DD + vds + 4);
            }
        }

        // ---- O += P @ V ----
        #pragma unroll
        for (int k16 = 0; k16 < 4; k16++) {
            uint32_t bb[8][2];
            #pragma unroll
            for (int j = 0; j < 8; j++) {
                const int w0 = (8 * j + g) * VST + 8 * k16 + tig;
                bb[j][0] = Vts[w0];
                bb[j][1] = Vts[w0 + 4];
            }
            #pragma unroll
            for (int mt = 0; mt < 2; mt++)
                #pragma unroll
                for (int j = 0; j < 8; j++)
                    mma16(of[mt][j], pa[mt][k16], bb[j]);
        }

        // ---- convert + store next tile, single barrier ----
        if (more) {
            uint32_t* dst = sm + ((kt + 1) & 1) * STG;
            #pragma unroll
            for (int i = 0; i < 8; i++)
                *(uint2*)&dst[(kr + 8 * i) * RW + kc4 / 2] =
                    make_uint2(f22h(kf[i].x, kf[i].y), f22h(kf[i].z, kf[i].w));
            uint32_t* dstV = dst + VOFF;
            #pragma unroll
            for (int i2 = 0; i2 < 2; i2++) {
                const int rp = vrp + 16 * i2;
                const float* fa  = (const float*)&va0[i2];
                const float* fa1 = (const float*)&va1[i2];
                const float* fb  = (const float*)&vb0[i2];
                const float* fb1 = (const float*)&vb1[i2];
                #pragma unroll
                for (int e = 0; e < 4; e++) {
                    dstV[(vds + e) * VST + rp]     = f22h(fa[e],  fb[e]);
                    dstV[(vds + e + 4) * VST + rp] = f22h(fa1[e], fb1[e]);
                }
            }
        }
        __syncthreads();
    }

    // ---- normalize + write context ----
    #pragma unroll
    for (int mt = 0; mt < 2; mt++) {
        const float inv0 = 1.f / lrow[mt][0], inv1 = 1.f / lrow[mt][1];
        const size_t orow = (size_t)(b * SS + qt * 128 + wr0 + mt * 16 + g);
        #pragma unroll
        for (int j = 0; j < 8; j++) {
            const int n = h * 64 + j * 8 + 2 * tig;
            *(float2*)&g_ctx[orow * DD + n] =
                make_float2(of[mt][j][0] * inv0, of[mt][j][1] * inv0);
            *(float2*)&g_ctx[(orow + 8) * DD + n] =
                make_float2(of[mt][j][2] * inv1, of[mt][j][3] * inv1);
        }
    }
}

// ---------------------------------------------------------------------------
extern "C" void kernel_launch(void* const* d_in, const int* in_sizes, int n_in,
                              void* d_out, int out_size)
{
    (void)in_sizes; (void)n_in; (void)out_size;
    const float* q  = (const float*)d_in[0];
    const float* k  = (const float*)d_in[1];
    const float* v  = (const float*)d_in[2];
    const float* wq = (const float*)d_in[3];
    const float* bq = (const float*)d_in[4];
    const float* wk = (const float*)d_in[5];
    const float* bk = (const float*)d_in[6];
    const float* wv = (const float*)d_in[7];
    const float* bv = (const float*)d_in[8];
    const float* wo = (const float*)d_in[9];
    const float* bo = (const float*)d_in[10];
    float* out = (float*)d_out;

    float *gq, *gk, *gv, *gctx;
    cudaGetSymbolAddress((void**)&gq,   g_Q);
    cudaGetSymbolAddress((void**)&gk,   g_K);
    cudaGetSymbolAddress((void**)&gv,   g_V);
    cudaGetSymbolAddress((void**)&gctx, g_ctx);

    cudaFuncSetAttribute(gemm_tc, cudaFuncAttributeMaxDynamicSharedMemorySize, GEMM_SMEM);
    cudaFuncSetAttribute(attn_tc, cudaFuncAttributeMaxDynamicSharedMemorySize, ATTN_SMEM);

    // fused Q/K/V projections: one launch, grid.z = 3
    gemm_tc<<<dim3(DD / 128, MM / 128, 3), 256, GEMM_SMEM>>>(
        q, k, v, wq, wk, wv, bq, bk, bv, gq, gk, gv);

    attn_tc<<<dim3(SS / 128, BB * HH), 128, ATTN_SMEM>>>();

    // output projection
    gemm_tc<<<dim3(DD / 128, MM / 128, 1), 256, GEMM_SMEM>>>(
        gctx, gctx, gctx, wo, wo, wo, bo, bo, bo, out, out, out);
}

// round 15
// speedup vs baseline: 1.7136x; 1.0336x over previous
#include <cuda_runtime.h>
#include <cuda_fp16.h>
#include <math.h>
#include <stdint.h>

#define BB 2
#define SS 2048
#define DD 1024
#define HH 16
#define MM (BB*SS)

// Scratch (allocation-free rule: __device__ globals)
__device__ float g_Q[(size_t)MM * DD];
__device__ float g_K[(size_t)MM * DD];
__device__ float g_V[(size_t)MM * DD];
__device__ float g_ctx[(size_t)MM * DD];

// fp16 MMA: D(16x8,f32) += A(16x16,f16) @ B(16x8,f16)
__device__ __forceinline__ void mma16(float* d, const uint32_t* a, const uint32_t* b) {
    asm volatile(
        "mma.sync.aligned.m16n8k16.row.col.f32.f16.f16.f32 "
        "{%0,%1,%2,%3}, {%4,%5,%6,%7}, {%8,%9}, {%0,%1,%2,%3};\n"
        : "+f"(d[0]), "+f"(d[1]), "+f"(d[2]), "+f"(d[3])
        : "r"(a[0]), "r"(a[1]), "r"(a[2]), "r"(a[3]), "r"(b[0]), "r"(b[1]));
}
__device__ __forceinline__ uint32_t f22h(float lo, float hi) {
    __half2 h = __floats2half2_rn(lo, hi);   // .x = lo (low 16 bits)
    return *(uint32_t*)&h;
}

// ===========================================================================
// GEMM: C = A @ W + bias (fp16 mma.sync m16n8k16, fp32 accum).
// Block 128x128, BK=32, 128 threads = 4 warps as 2(M) x 2(N), warp tile
// 64x64 -> fragment traffic per chunk drops 48KB -> 32KB vs the 8-warp
// version. Fill mappings keep 4-lines-per-LDG + conflict-free STS:
//   A: 8 lanes/row, rows rA+16i (8 LDG.128 / 8 STS.64 per thread)
//   B: warp loads k-row pairs (2p, 2p+1), p = warp+4i (8 LDG.128 / 4 STS.128)
// A smem [row][k-pair] stride 20; B smem [k-pair][n] stride 136 (fragment
// layouts unchanged from the proven R13 kernel). Ping-pong, register
// prefetch, store-side convert, 1 barrier/chunk.
// ===========================================================================
#define SA 20
#define SBW 136
#define GA2 (128 * SA)                    // 2560 words per A stage
#define GB2 (16 * SBW)                    // 2176 words per B stage
#define GEMM_SMEM ((2 * GA2 + 2 * GB2) * 4)   // 37888 B

__global__ void __launch_bounds__(128) gemm_tc(
    const float* __restrict__ A0, const float* __restrict__ A1, const float* __restrict__ A2,
    const float* __restrict__ W0, const float* __restrict__ W1, const float* __restrict__ W2,
    const float* __restrict__ b0, const float* __restrict__ b1, const float* __restrict__ b2,
    float* __restrict__ C0, float* __restrict__ C1, float* __restrict__ C2)
{
    extern __shared__ uint32_t gsm[];
    const int z = blockIdx.z;
    const float* A = (z == 0) ? A0 : (z == 1) ? A1 : A2;
    const float* W = (z == 0) ? W0 : (z == 1) ? W1 : W2;
    const float* bias = (z == 0) ? b0 : (z == 1) ? b1 : b2;
    float* C = (z == 0) ? C0 : (z == 1) ? C1 : C2;

    const int tid  = threadIdx.x;
    const int lane = tid & 31, warp = tid >> 5;
    const int g = lane >> 2, tig = lane & 3;
    const int wm = warp >> 1, wn = warp & 1;
    const int row0 = blockIdx.y * 128, col0 = blockIdx.x * 128;

    // fill mappings (coalesced, 128 threads)
    const int rA = tid >> 3, cA = (tid & 7) * 4;   // A: rows rA+16i, i=0..7
    const float* Ap = A + (size_t)(row0 + rA) * DD + cA;
    const float* WpB = W + (size_t)(2 * warp) * DD + col0 + 4 * lane;

    float acc[4][8][4] = {};
    float4 av[8], bv[8];

    auto loadAB = [&](int k0) {
        #pragma unroll
        for (int i = 0; i < 8; i++)
            av[i] = *(const float4*)(Ap + k0 + (size_t)(16 * i) * DD);
        #pragma unroll
        for (int i = 0; i < 4; i++) {
            bv[2 * i]     = *(const float4*)(WpB + (size_t)(k0 + 8 * i) * DD);
            bv[2 * i + 1] = *(const float4*)(WpB + (size_t)(k0 + 8 * i + 1) * DD);
        }
    };
    auto storeStage = [&](int s) {
        uint32_t* As = gsm + s * GA2;
        uint32_t* Bs = gsm + 2 * GA2 + s * GB2;
        #pragma unroll
        for (int i = 0; i < 8; i++) {
            uint2 t;
            t.x = f22h(av[i].x, av[i].y);
            t.y = f22h(av[i].z, av[i].w);
            *(uint2*)&As[(rA + 16 * i) * SA + cA / 2] = t;
        }
        #pragma unroll
        for (int i = 0; i < 4; i++) {
            const float* e = (const float*)&bv[2 * i];
            const float* o = (const float*)&bv[2 * i + 1];
            uint4 t;
            t.x = f22h(e[0], o[0]); t.y = f22h(e[1], o[1]);
            t.z = f22h(e[2], o[2]); t.w = f22h(e[3], o[3]);
            *(uint4*)&Bs[(warp + 4 * i) * SBW + 4 * lane] = t;
        }
    };

    // ---- prologue: chunk 0 -> stage 0 ----
    loadAB(0);
    storeStage(0);
    __syncthreads();

    for (int c = 0; c < 32; c++) {
        if (c + 1 < 32) loadAB((c + 1) * 32);

        const uint32_t* As = gsm + (c & 1) * GA2;
        const uint32_t* Bs = gsm + 2 * GA2 + (c & 1) * GB2;

        #pragma unroll
        for (int k16 = 0; k16 < 2; k16++) {
            uint32_t af[4][4], bf[8][2];
            #pragma unroll
            for (int mt = 0; mt < 4; mt++) {
                const int r = wm * 64 + mt * 16 + g;
                af[mt][0] = As[r * SA + k16 * 8 + tig];
                af[mt][1] = As[(r + 8) * SA + k16 * 8 + tig];
                af[mt][2] = As[r * SA + k16 * 8 + tig + 4];
                af[mt][3] = As[(r + 8) * SA + k16 * 8 + tig + 4];
            }
            #pragma unroll
            for (int j = 0; j < 8; j++) {
                const int n = wn * 64 + j * 8 + g;
                bf[j][0] = Bs[(k16 * 8 + tig) * SBW + n];
                bf[j][1] = Bs[(k16 * 8 + tig + 4) * SBW + n];
            }
            #pragma unroll
            for (int mt = 0; mt < 4; mt++)
                #pragma unroll
                for (int j = 0; j < 8; j++)
                    mma16(acc[mt][j], af[mt], bf[j]);
        }

        if (c + 1 < 32) {
            storeStage((c + 1) & 1);
            __syncthreads();
        }
    }

    // epilogue: bias + store
    #pragma unroll
    for (int mt = 0; mt < 4; mt++) {
        #pragma unroll
        for (int j = 0; j < 8; j++) {
            const int n = col0 + wn * 64 + j * 8 + 2 * tig;
            const float bb0 = bias[n], bb1 = bias[n + 1];
            const int r = row0 + wm * 64 + mt * 16 + g;
            *(float2*)&C[(size_t)r * DD + n] =
                make_float2(acc[mt][j][0] + bb0, acc[mt][j][1] + bb1);
            *(float2*)&C[(size_t)(r + 8) * DD + n] =
                make_float2(acc[mt][j][2] + bb0, acc[mt][j][3] + bb1);
        }
    }
}

// ===========================================================================
// Flash attention, fp16 mma.sync m16n8k16, fp32 accumulate.
// Byte-identical to the proven R13/R14 kernel (~155us).
// ===========================================================================
#define RW 36                       // K/Q row stride in 4B words (72 halves)
#define VST 37                      // V row stride in words
#define KWD (64 * RW)
#define VWD (64 * VST)
#define VOFF KWD
#define STG (KWD + VWD)
#define ATTN_SMEM (2 * STG * 4)     // 37376 B
#define NT (SS / 64)

__global__ void __launch_bounds__(128) attn_tc()
{
    extern __shared__ uint32_t sm[];

    const int tid  = threadIdx.x;
    const int lane = tid & 31, warp = tid >> 5;
    const int g = lane >> 2, tig = lane & 3;
    const int wr0 = warp * 32;
    const int qt = blockIdx.x;
    const int b  = blockIdx.y >> 4;
    const int h  = blockIdx.y & 15;

    const float* Qg = g_Q + (size_t)(b * SS + qt * 128) * DD + h * 64;
    const float* Kg = g_K + (size_t)(b * SS) * DD + h * 64;
    const float* Vg = g_V + (size_t)(b * SS) * DD + h * 64;

    const int kr = tid >> 4, kc4 = (tid & 15) * 4;
    const int vrp = tid >> 3, vds = (tid & 7) * 8;

    #pragma unroll
    for (int p = 0; p < 16; p++) {
        const int i = tid + 128 * p;
        const int r = i >> 4, c4 = (i & 15) * 4;
        float4 qv = *(const float4*)(Qg + (size_t)r * DD + c4);
        *(uint2*)&sm[STG + r * RW + c4 / 2] =
            make_uint2(f22h(qv.x * 0.125f, qv.y * 0.125f),
                       f22h(qv.z * 0.125f, qv.w * 0.125f));
    }
    __syncthreads();

    uint32_t qa[2][4][4];
    #pragma unroll
    for (int mt = 0; mt < 2; mt++) {
        const int r = wr0 + mt * 16 + g;
        #pragma unroll
        for (int k16 = 0; k16 < 4; k16++) {
            const int base = STG + r * RW + k16 * 8 + tig;
            qa[mt][k16][0] = sm[base];
            qa[mt][k16][1] = sm[base + 8 * RW];
            qa[mt][k16][2] = sm[base + 4];
            qa[mt][k16][3] = sm[base + 8 * RW + 4];
        }
    }
    __syncthreads();

    {
        #pragma unroll
        for (int i = 0; i < 8; i++) {
            float4 kf = *(const float4*)(Kg + (size_t)(kr + 8 * i) * DD + kc4);
            *(uint2*)&sm[(kr + 8 * i) * RW + kc4 / 2] =
                make_uint2(f22h(kf.x, kf.y), f22h(kf.z, kf.w));
        }
        #pragma unroll
        for (int i2 = 0; i2 < 2; i2++) {
            const int rp = vrp + 16 * i2;
            float4 a0 = *(const float4*)(Vg + (size_t)(2 * rp) * DD + vds);
            float4 a1 = *(const float4*)(Vg + (size_t)(2 * rp) * DD + vds + 4);
            float4 c0 = *(const float4*)(Vg + (size_t)(2 * rp + 1) * DD + vds);
            float4 c1 = *(const float4*)(Vg + (size_t)(2 * rp + 1) * DD + vds + 4);
            const float* fa = (const float*)&a0;
            const float* fa1 = (const float*)&a1;
            const float* fb = (const float*)&c0;
            const float* fb1 = (const float*)&c1;
            #pragma unroll
            for (int e = 0; e < 4; e++) {
                sm[VOFF + (vds + e) * VST + rp]     = f22h(fa[e],  fb[e]);
                sm[VOFF + (vds + e + 4) * VST + rp] = f22h(fa1[e], fb1[e]);
            }
        }
    }
    __syncthreads();

    float of[2][8][4] = {};
    float mrow[2][2] = {{-1e30f, -1e30f}, {-1e30f, -1e30f}};
    float lrow[2][2] = {{0.f, 0.f}, {0.f, 0.f}};

    for (int kt = 0; kt < NT; kt++) {
        const uint32_t* Ks  = sm + (kt & 1) * STG;
        const uint32_t* Vts = sm + (kt & 1) * STG + VOFF;

        float sf[2][8][4] = {};
        #pragma unroll
        for (int k16 = 0; k16 < 4; k16++) {
            uint32_t bf[8][2];
            #pragma unroll
            for (int j = 0; j < 8; j++) {
                const int w0 = (8 * j + g) * RW + 8 * k16 + tig;
                bf[j][0] = Ks[w0];
                bf[j][1] = Ks[w0 + 4];
            }
            #pragma unroll
            for (int mt = 0; mt < 2; mt++)
                #pragma unroll
                for (int j = 0; j < 8; j++)
                    mma16(sf[mt][j], qa[mt][k16], bf[j]);
        }

        #pragma unroll
        for (int mt = 0; mt < 2; mt++) {
            #pragma unroll
            for (int i = 0; i < 2; i++) {
                float mx = -1e30f;
                #pragma unroll
                for (int j = 0; j < 8; j++)
                    mx = fmaxf(mx, fmaxf(sf[mt][j][2 * i], sf[mt][j][2 * i + 1]));
                mx = fmaxf(mx, __shfl_xor_sync(0xffffffffu, mx, 1));
                mx = fmaxf(mx, __shfl_xor_sync(0xffffffffu, mx, 2));
                const float mn = fmaxf(mrow[mt][i], mx);
                const float corr = __expf(mrow[mt][i] - mn);
                mrow[mt][i] = mn;
                float rs = 0.f;
                #pragma unroll
                for (int j = 0; j < 8; j++) {
                    sf[mt][j][2 * i]     = __expf(sf[mt][j][2 * i] - mn);
                    sf[mt][j][2 * i + 1] = __expf(sf[mt][j][2 * i + 1] - mn);
                    rs += sf[mt][j][2 * i] + sf[mt][j][2 * i + 1];
                }
                rs += __shfl_xor_sync(0xffffffffu, rs, 1);
                rs += __shfl_xor_sync(0xffffffffu, rs, 2);
                lrow[mt][i] = lrow[mt][i] * corr + rs;
                #pragma unroll
                for (int j = 0; j < 8; j++) {
                    of[mt][j][2 * i]     *= corr;
                    of[mt][j][2 * i + 1] *= corr;
                }
            }
        }

        uint32_t pa[2][4][4];
        #pragma unroll
        for (int mt = 0; mt < 2; mt++)
            #pragma unroll
            for (int k16 = 0; k16 < 4; k16++) {
                pa[mt][k16][0] = f22h(sf[mt][2 * k16][0],     sf[mt][2 * k16][1]);
                pa[mt][k16][1] = f22h(sf[mt][2 * k16][2],     sf[mt][2 * k16][3]);
                pa[mt][k16][2] = f22h(sf[mt][2 * k16 + 1][0], sf[mt][2 * k16 + 1][1]);
                pa[mt][k16][3] = f22h(sf[mt][2 * k16 + 1][2], sf[mt][2 * k16 + 1][3]);
            }

        const bool more = (kt + 1 < NT);
        float4 kf[8], va0[2], va1[2], vb0[2], vb1[2];
        if (more) {
            const float* Kt = Kg + (size_t)((kt + 1) * 64) * DD;
            const float* Vt = Vg + (size_t)((kt + 1) * 64) * DD;
            #pragma unroll
            for (int i = 0; i < 8; i++)
                kf[i] = *(const float4*)(Kt + (size_t)(kr + 8 * i) * DD + kc4);
            #pragma unroll
            for (int i2 = 0; i2 < 2; i2++) {
                const int rp = vrp + 16 * i2;
                va0[i2] = *(const float4*)(Vt + (size_t)(2 * rp) * DD + vds);
                va1[i2] = *(const float4*)(Vt + (size_t)(2 * rp) * DD + vds + 4);
                vb0[i2] = *(const float4*)(Vt + (size_t)(2 * rp + 1) * DD + vds);
                vb1[i2] = *(const float4*)(Vt + (size_t)(2 * rp + 1) * DD + vds + 4);
            }
        }

        #pragma unroll
        for (int k16 = 0; k16 < 4; k16++) {
            uint32_t bb[8][2];
            #pragma unroll
            for (int j = 0; j < 8; j++) {
                const int w0 = (8 * j + g) * VST + 8 * k16 + tig;
                bb[j][0] = Vts[w0];
                bb[j][1] = Vts[w0 + 4];
            }
            #pragma unroll
            for (int mt = 0; mt < 2; mt++)
                #pragma unroll
                for (int j = 0; j < 8; j++)
                    mma16(of[mt][j], pa[mt][k16], bb[j]);
        }

        if (more) {
            uint32_t* dst = sm + ((kt + 1) & 1) * STG;
            #pragma unroll
            for (int i = 0; i < 8; i++)
                *(uint2*)&dst[(kr + 8 * i) * RW + kc4 / 2] =
                    make_uint2(f22h(kf[i].x, kf[i].y), f22h(kf[i].z, kf[i].w));
            uint32_t* dstV = dst + VOFF;
            #pragma unroll
            for (int i2 = 0; i2 < 2; i2++) {
                const int rp = vrp + 16 * i2;
                const float* fa  = (const float*)&va0[i2];
                const float* fa1 = (const float*)&va1[i2];
                const float* fb  = (const float*)&vb0[i2];
                const float* fb1 = (const float*)&vb1[i2];
                #pragma unroll
                for (int e = 0; e < 4; e++) {
                    dstV[(vds + e) * VST + rp]     = f22h(fa[e],  fb[e]);
                    dstV[(vds + e + 4) * VST + rp] = f22h(fa1[e], fb1[e]);
                }
            }
        }
        __syncthreads();
    }

    #pragma unroll
    for (int mt = 0; mt < 2; mt++) {
        const float inv0 = 1.f / lrow[mt][0], inv1 = 1.f / lrow[mt][1];
        const size_t orow = (size_t)(b * SS + qt * 128 + wr0 + mt * 16 + g);
        #pragma unroll
        for (int j = 0; j < 8; j++) {
            const int n = h * 64 + j * 8 + 2 * tig;
            *(float2*)&g_ctx[orow * DD + n] =
                make_float2(of[mt][j][0] * inv0, of[mt][j][1] * inv0);
            *(float2*)&g_ctx[(orow + 8) * DD + n] =
                make_float2(of[mt][j][2] * inv1, of[mt][j][3] * inv1);
        }
    }
}

// ---------------------------------------------------------------------------
extern "C" void kernel_launch(void* const* d_in, const int* in_sizes, int n_in,
                              void* d_out, int out_size)
{
    (void)in_sizes; (void)n_in; (void)out_size;
    const float* q  = (const float*)d_in[0];
    const float* k  = (const float*)d_in[1];
    const float* v  = (const float*)d_in[2];
    const float* wq = (const float*)d_in[3];
    const float* bq = (const float*)d_in[4];
    const float* wk = (const float*)d_in[5];
    const float* bk = (const float*)d_in[6];
    const float* wv = (const float*)d_in[7];
    const float* bv = (const float*)d_in[8];
    const float* wo = (const float*)d_in[9];
    const float* bo = (const float*)d_in[10];
    float* out = (float*)d_out;

    float *gq, *gk, *gv, *gctx;
    cudaGetSymbolAddress((void**)&gq,   g_Q);
    cudaGetSymbolAddress((void**)&gk,   g_K);
    cudaGetSymbolAddress((void**)&gv,   g_V);
    cudaGetSymbolAddress((void**)&gctx, g_ctx);

    cudaFuncSetAttribute(gemm_tc, cudaFuncAttributeMaxDynamicSharedMemorySize, GEMM_SMEM);
    cudaFuncSetAttribute(attn_tc, cudaFuncAttributeMaxDynamicSharedMemorySize, ATTN_SMEM);

    // fused Q/K/V projections: one launch, grid.z = 3
    gemm_tc<<<dim3(DD / 128, MM / 128, 3), 128, GEMM_SMEM>>>(
        q, k, v, wq, wk, wv, bq, bk, bv, gq, gk, gv);

    attn_tc<<<dim3(SS / 128, BB * HH), 128, ATTN_SMEM>>>();

    // output projection
    gemm_tc<<<dim3(DD / 128, MM / 128, 1), 128, GEMM_SMEM>>>(
        gctx, gctx, gctx, wo, wo, wo, bo, bo, bo, out, out, out);
}

// round 16
// speedup vs baseline: 1.8574x; 1.0839x over previous
#include <cuda_runtime.h>
#include <cuda_fp16.h>
#include <math.h>
#include <stdint.h>

#define BB 2
#define SS 2048
#define DD 1024
#define DW (DD / 2)                 // row stride in uint32 words (half2)
#define HH 16
#define MM (BB*SS)

// Scratch (allocation-free rule: __device__ globals) — fp16 packed as uint32
__device__ uint32_t g_Qh[(size_t)MM * DW];
__device__ uint32_t g_Kh[(size_t)MM * DW];
__device__ uint32_t g_Vh[(size_t)MM * DW];
__device__ uint32_t g_Ch[(size_t)MM * DW];

// fp16 MMA: D(16x8,f32) += A(16x16,f16) @ B(16x8,f16)
__device__ __forceinline__ void mma16(float* d, const uint32_t* a, const uint32_t* b) {
    asm volatile(
        "mma.sync.aligned.m16n8k16.row.col.f32.f16.f16.f32 "
        "{%0,%1,%2,%3}, {%4,%5,%6,%7}, {%8,%9}, {%0,%1,%2,%3};\n"
        : "+f"(d[0]), "+f"(d[1]), "+f"(d[2]), "+f"(d[3])
        : "r"(a[0]), "r"(a[1]), "r"(a[2]), "r"(a[3]), "r"(b[0]), "r"(b[1]));
}
__device__ __forceinline__ uint32_t f22h(float lo, float hi) {
    __half2 h = __floats2half2_rn(lo, hi);   // .x = lo (low 16 bits)
    return *(uint32_t*)&h;
}

// ===========================================================================
// GEMM #1 (QKV projections): C_h = fp16(A @ W + bias) [* 0.125 for z==0].
// Structure identical to the proven R15 gemm (128x128 tile, BK=32, 4 warps
// 64x64, ping-pong, register prefetch, store-side convert); only the
// epilogue changes (packed half2 stores, halved write bytes).
// ===========================================================================
#define SA 20
#define SBW 136
#define GA2 (128 * SA)
#define GB2 (16 * SBW)
#define GEMM_SMEM ((2 * GA2 + 2 * GB2) * 4)   // 37888 B

__global__ void __launch_bounds__(128) gemm_qkv(
    const float* __restrict__ A0, const float* __restrict__ A1, const float* __restrict__ A2,
    const float* __restrict__ W0, const float* __restrict__ W1, const float* __restrict__ W2,
    const float* __restrict__ b0, const float* __restrict__ b1, const float* __restrict__ b2,
    uint32_t* __restrict__ C0, uint32_t* __restrict__ C1, uint32_t* __restrict__ C2)
{
    extern __shared__ uint32_t gsm[];
    const int z = blockIdx.z;
    const float* A = (z == 0) ? A0 : (z == 1) ? A1 : A2;
    const float* W = (z == 0) ? W0 : (z == 1) ? W1 : W2;
    const float* bias = (z == 0) ? b0 : (z == 1) ? b1 : b2;
    uint32_t* Ch = (z == 0) ? C0 : (z == 1) ? C1 : C2;
    const float sc = (z == 0) ? 0.125f : 1.0f;

    const int tid  = threadIdx.x;
    const int lane = tid & 31, warp = tid >> 5;
    const int g = lane >> 2, tig = lane & 3;
    const int wm = warp >> 1, wn = warp & 1;
    const int row0 = blockIdx.y * 128, col0 = blockIdx.x * 128;

    const int rA = tid >> 3, cA = (tid & 7) * 4;
    const float* Ap = A + (size_t)(row0 + rA) * DD + cA;
    const float* WpB = W + (size_t)(2 * warp) * DD + col0 + 4 * lane;

    float acc[4][8][4] = {};
    float4 av[8], bv[8];

    auto loadAB = [&](int k0) {
        #pragma unroll
        for (int i = 0; i < 8; i++)
            av[i] = *(const float4*)(Ap + k0 + (size_t)(16 * i) * DD);
        #pragma unroll
        for (int i = 0; i < 4; i++) {
            bv[2 * i]     = *(const float4*)(WpB + (size_t)(k0 + 8 * i) * DD);
            bv[2 * i + 1] = *(const float4*)(WpB + (size_t)(k0 + 8 * i + 1) * DD);
        }
    };
    auto storeStage = [&](int s) {
        uint32_t* As = gsm + s * GA2;
        uint32_t* Bs = gsm + 2 * GA2 + s * GB2;
        #pragma unroll
        for (int i = 0; i < 8; i++) {
            uint2 t;
            t.x = f22h(av[i].x, av[i].y);
            t.y = f22h(av[i].z, av[i].w);
            *(uint2*)&As[(rA + 16 * i) * SA + cA / 2] = t;
        }
        #pragma unroll
        for (int i = 0; i < 4; i++) {
            const float* e = (const float*)&bv[2 * i];
            const float* o = (const float*)&bv[2 * i + 1];
            uint4 t;
            t.x = f22h(e[0], o[0]); t.y = f22h(e[1], o[1]);
            t.z = f22h(e[2], o[2]); t.w = f22h(e[3], o[3]);
            *(uint4*)&Bs[(warp + 4 * i) * SBW + 4 * lane] = t;
        }
    };

    loadAB(0);
    storeStage(0);
    __syncthreads();

    for (int c = 0; c < 32; c++) {
        if (c + 1 < 32) loadAB((c + 1) * 32);

        const uint32_t* As = gsm + (c & 1) * GA2;
        const uint32_t* Bs = gsm + 2 * GA2 + (c & 1) * GB2;

        #pragma unroll
        for (int k16 = 0; k16 < 2; k16++) {
            uint32_t af[4][4], bf[8][2];
            #pragma unroll
            for (int mt = 0; mt < 4; mt++) {
                const int r = wm * 64 + mt * 16 + g;
                af[mt][0] = As[r * SA + k16 * 8 + tig];
                af[mt][1] = As[(r + 8) * SA + k16 * 8 + tig];
                af[mt][2] = As[r * SA + k16 * 8 + tig + 4];
                af[mt][3] = As[(r + 8) * SA + k16 * 8 + tig + 4];
            }
            #pragma unroll
            for (int j = 0; j < 8; j++) {
                const int n = wn * 64 + j * 8 + g;
                bf[j][0] = Bs[(k16 * 8 + tig) * SBW + n];
                bf[j][1] = Bs[(k16 * 8 + tig + 4) * SBW + n];
            }
            #pragma unroll
            for (int mt = 0; mt < 4; mt++)
                #pragma unroll
                for (int j = 0; j < 8; j++)
                    mma16(acc[mt][j], af[mt], bf[j]);
        }

        if (c + 1 < 32) {
            storeStage((c + 1) & 1);
            __syncthreads();
        }
    }

    // epilogue: bias (+scale) -> packed fp16
    #pragma unroll
    for (int mt = 0; mt < 4; mt++) {
        #pragma unroll
        for (int j = 0; j < 8; j++) {
            const int n = col0 + wn * 64 + j * 8 + 2 * tig;
            const float bb0 = bias[n], bb1 = bias[n + 1];
            const int r = row0 + wm * 64 + mt * 16 + g;
            Ch[(size_t)r * DW + n / 2] =
                f22h((acc[mt][j][0] + bb0) * sc, (acc[mt][j][1] + bb1) * sc);
            Ch[(size_t)(r + 8) * DW + n / 2] =
                f22h((acc[mt][j][2] + bb0) * sc, (acc[mt][j][3] + bb1) * sc);
        }
    }
}

// ===========================================================================
// GEMM #2 (output projection): C = ctx_h(fp16) @ W + bias, fp32 out.
// A fill is a straight uint4 copy from fp16 global (no conversion).
// ===========================================================================
__global__ void __launch_bounds__(128) gemm_out(
    const uint32_t* __restrict__ Ah, const float* __restrict__ W,
    const float* __restrict__ bias, float* __restrict__ C)
{
    extern __shared__ uint32_t gsm[];

    const int tid  = threadIdx.x;
    const int lane = tid & 31, warp = tid >> 5;
    const int g = lane >> 2, tig = lane & 3;
    const int wm = warp >> 1, wn = warp & 1;
    const int row0 = blockIdx.y * 128, col0 = blockIdx.x * 128;

    const int rA = tid >> 2, cw = (tid & 3) * 4;   // rows rA+32i, 4 words each
    const uint32_t* Aph = Ah + (size_t)(row0 + rA) * DW + cw;
    const float* WpB = W + (size_t)(2 * warp) * DD + col0 + 4 * lane;

    float acc[4][8][4] = {};
    uint4 avu[4];
    float4 bv[8];

    auto loadAB = [&](int c2) {
        const int kw = c2 * 16;          // chunk offset in words
        #pragma unroll
        for (int i = 0; i < 4; i++)
            avu[i] = *(const uint4*)(Aph + kw + (size_t)(32 * i) * DW);
        const int k0 = c2 * 32;
        #pragma unroll
        for (int i = 0; i < 4; i++) {
            bv[2 * i]     = *(const float4*)(WpB + (size_t)(k0 + 8 * i) * DD);
            bv[2 * i + 1] = *(const float4*)(WpB + (size_t)(k0 + 8 * i + 1) * DD);
        }
    };
    auto storeStage = [&](int s) {
        uint32_t* As = gsm + s * GA2;
        uint32_t* Bs = gsm + 2 * GA2 + s * GB2;
        #pragma unroll
        for (int i = 0; i < 4; i++)
            *(uint4*)&As[(rA + 32 * i) * SA + cw] = avu[i];
        #pragma unroll
        for (int i = 0; i < 4; i++) {
            const float* e = (const float*)&bv[2 * i];
            const float* o = (const float*)&bv[2 * i + 1];
            uint4 t;
            t.x = f22h(e[0], o[0]); t.y = f22h(e[1], o[1]);
            t.z = f22h(e[2], o[2]); t.w = f22h(e[3], o[3]);
            *(uint4*)&Bs[(warp + 4 * i) * SBW + 4 * lane] = t;
        }
    };

    loadAB(0);
    storeStage(0);
    __syncthreads();

    for (int c = 0; c < 32; c++) {
        if (c + 1 < 32) loadAB(c + 1);

        const uint32_t* As = gsm + (c & 1) * GA2;
        const uint32_t* Bs = gsm + 2 * GA2 + (c & 1) * GB2;

        #pragma unroll
        for (int k16 = 0; k16 < 2; k16++) {
            uint32_t af[4][4], bf[8][2];
            #pragma unroll
            for (int mt = 0; mt < 4; mt++) {
                const int r = wm * 64 + mt * 16 + g;
                af[mt][0] = As[r * SA + k16 * 8 + tig];
                af[mt][1] = As[(r + 8) * SA + k16 * 8 + tig];
                af[mt][2] = As[r * SA + k16 * 8 + tig + 4];
                af[mt][3] = As[(r + 8) * SA + k16 * 8 + tig + 4];
            }
            #pragma unroll
            for (int j = 0; j < 8; j++) {
                const int n = wn * 64 + j * 8 + g;
                bf[j][0] = Bs[(k16 * 8 + tig) * SBW + n];
                bf[j][1] = Bs[(k16 * 8 + tig + 4) * SBW + n];
            }
            #pragma unroll
            for (int mt = 0; mt < 4; mt++)
                #pragma unroll
                for (int j = 0; j < 8; j++)
                    mma16(acc[mt][j], af[mt], bf[j]);
        }

        if (c + 1 < 32) {
            storeStage((c + 1) & 1);
            __syncthreads();
        }
    }

    #pragma unroll
    for (int mt = 0; mt < 4; mt++) {
        #pragma unroll
        for (int j = 0; j < 8; j++) {
            const int n = col0 + wn * 64 + j * 8 + 2 * tig;
            const float bb0 = bias[n], bb1 = bias[n + 1];
            const int r = row0 + wm * 64 + mt * 16 + g;
            *(float2*)&C[(size_t)r * DD + n] =
                make_float2(acc[mt][j][0] + bb0, acc[mt][j][1] + bb1);
            *(float2*)&C[(size_t)(r + 8) * DD + n] =
                make_float2(acc[mt][j][2] + bb0, acc[mt][j][3] + bb1);
        }
    }
}

// ===========================================================================
// Flash attention, fp16 mma.sync. Fragment pipeline identical to proven R13;
// fills are now pure fp16 copies (Q pre-scaled by GEMM; K direct; V transpose
// via byte_perm, no conversions). Epilogue writes fp16 ctx.
// ===========================================================================
#define RW 36
#define VST 37
#define KWD (64 * RW)
#define VWD (64 * VST)
#define VOFF KWD
#define STG (KWD + VWD)
#define ATTN_SMEM (2 * STG * 4)     // 37376 B
#define NT (SS / 64)

__global__ void __launch_bounds__(128) attn_tc()
{
    extern __shared__ uint32_t sm[];

    const int tid  = threadIdx.x;
    const int lane = tid & 31, warp = tid >> 5;
    const int g = lane >> 2, tig = lane & 3;
    const int wr0 = warp * 32;
    const int qt = blockIdx.x;
    const int b  = blockIdx.y >> 4;
    const int h  = blockIdx.y & 15;

    const uint32_t* Qgh = g_Qh + (size_t)(b * SS + qt * 128) * DW + h * 32;
    const uint32_t* Kgh = g_Kh + (size_t)(b * SS) * DW + h * 32;
    const uint32_t* Vgh = g_Vh + (size_t)(b * SS) * DW + h * 32;

    // fill mappings
    const int fr = tid >> 3, fc = (tid & 7) * 4;     // Q/K: 8 threads/row, uint4
    const int vrp = tid >> 3, vds = (tid & 7) * 8;   // V: key-pair rows

    // ---- prologue: stage Q (already scaled fp16) into stage-1 region ----
    #pragma unroll
    for (int i = 0; i < 8; i++)
        *(uint4*)&sm[STG + (fr + 16 * i) * RW + fc] =
            *(const uint4*)(Qgh + (size_t)(fr + 16 * i) * DW + fc);
    __syncthreads();

    // ---- extract persistent Q A-fragments ----
    uint32_t qa[2][4][4];
    #pragma unroll
    for (int mt = 0; mt < 2; mt++) {
        const int r = wr0 + mt * 16 + g;
        #pragma unroll
        for (int k16 = 0; k16 < 4; k16++) {
            const int base = STG + r * RW + k16 * 8 + tig;
            qa[mt][k16][0] = sm[base];
            qa[mt][k16][1] = sm[base + 8 * RW];
            qa[mt][k16][2] = sm[base + 4];
            qa[mt][k16][3] = sm[base + 8 * RW + 4];
        }
    }
    __syncthreads();   // Q reads done before stage-1 reuse

    // ---- fill tile 0 into stage 0 ----
    {
        #pragma unroll
        for (int i = 0; i < 4; i++)
            *(uint4*)&sm[(fr + 16 * i) * RW + fc] =
                *(const uint4*)(Kgh + (size_t)(fr + 16 * i) * DW + fc);
        #pragma unroll
        for (int i2 = 0; i2 < 2; i2++) {
            const int rp = vrp + 16 * i2;
            uint4 A = *(const uint4*)(Vgh + (size_t)(2 * rp) * DW + vds / 2);
            uint4 Bv = *(const uint4*)(Vgh + (size_t)(2 * rp + 1) * DW + vds / 2);
            sm[VOFF + (vds + 0) * VST + rp] = __byte_perm(A.x, Bv.x, 0x5410);
            sm[VOFF + (vds + 1) * VST + rp] = __byte_perm(A.x, Bv.x, 0x7632);
            sm[VOFF + (vds + 2) * VST + rp] = __byte_perm(A.y, Bv.y, 0x5410);
            sm[VOFF + (vds + 3) * VST + rp] = __byte_perm(A.y, Bv.y, 0x7632);
            sm[VOFF + (vds + 4) * VST + rp] = __byte_perm(A.z, Bv.z, 0x5410);
            sm[VOFF + (vds + 5) * VST + rp] = __byte_perm(A.z, Bv.z, 0x7632);
            sm[VOFF + (vds + 6) * VST + rp] = __byte_perm(A.w, Bv.w, 0x5410);
            sm[VOFF + (vds + 7) * VST + rp] = __byte_perm(A.w, Bv.w, 0x7632);
        }
    }
    __syncthreads();

    float of[2][8][4] = {};
    float mrow[2][2] = {{-1e30f, -1e30f}, {-1e30f, -1e30f}};
    float lrow[2][2] = {{0.f, 0.f}, {0.f, 0.f}};

    for (int kt = 0; kt < NT; kt++) {
        const uint32_t* Ks  = sm + (kt & 1) * STG;
        const uint32_t* Vts = sm + (kt & 1) * STG + VOFF;

        // ---- S = Qs @ K^T ----
        float sf[2][8][4] = {};
        #pragma unroll
        for (int k16 = 0; k16 < 4; k16++) {
            uint32_t bf[8][2];
            #pragma unroll
            for (int j = 0; j < 8; j++) {
                const int w0 = (8 * j + g) * RW + 8 * k16 + tig;
                bf[j][0] = Ks[w0];
                bf[j][1] = Ks[w0 + 4];
            }
            #pragma unroll
            for (int mt = 0; mt < 2; mt++)
                #pragma unroll
                for (int j = 0; j < 8; j++)
                    mma16(sf[mt][j], qa[mt][k16], bf[j]);
        }

        // ---- online softmax ----
        #pragma unroll
        for (int mt = 0; mt < 2; mt++) {
            #pragma unroll
            for (int i = 0; i < 2; i++) {
                float mx = -1e30f;
                #pragma unroll
                for (int j = 0; j < 8; j++)
                    mx = fmaxf(mx, fmaxf(sf[mt][j][2 * i], sf[mt][j][2 * i + 1]));
                mx = fmaxf(mx, __shfl_xor_sync(0xffffffffu, mx, 1));
                mx = fmaxf(mx, __shfl_xor_sync(0xffffffffu, mx, 2));
                const float mn = fmaxf(mrow[mt][i], mx);
                const float corr = __expf(mrow[mt][i] - mn);
                mrow[mt][i] = mn;
                float rs = 0.f;
                #pragma unroll
                for (int j = 0; j < 8; j++) {
                    sf[mt][j][2 * i]     = __expf(sf[mt][j][2 * i] - mn);
                    sf[mt][j][2 * i + 1] = __expf(sf[mt][j][2 * i + 1] - mn);
                    rs += sf[mt][j][2 * i] + sf[mt][j][2 * i + 1];
                }
                rs += __shfl_xor_sync(0xffffffffu, rs, 1);
                rs += __shfl_xor_sync(0xffffffffu, rs, 2);
                lrow[mt][i] = lrow[mt][i] * corr + rs;
                #pragma unroll
                for (int j = 0; j < 8; j++) {
                    of[mt][j][2 * i]     *= corr;
                    of[mt][j][2 * i + 1] *= corr;
                }
            }
        }

        // ---- pack P into PV A-fragments (registers only) ----
        uint32_t pa[2][4][4];
        #pragma unroll
        for (int mt = 0; mt < 2; mt++)
            #pragma unroll
            for (int k16 = 0; k16 < 4; k16++) {
                pa[mt][k16][0] = f22h(sf[mt][2 * k16][0],     sf[mt][2 * k16][1]);
                pa[mt][k16][1] = f22h(sf[mt][2 * k16][2],     sf[mt][2 * k16][3]);
                pa[mt][k16][2] = f22h(sf[mt][2 * k16 + 1][0], sf[mt][2 * k16 + 1][1]);
                pa[mt][k16][3] = f22h(sf[mt][2 * k16 + 1][2], sf[mt][2 * k16 + 1][3]);
            }

        // ---- issue next tile's global loads (hidden under PV) ----
        const bool more = (kt + 1 < NT);
        uint4 kfu[4], vau[2], vbu[2];
        if (more) {
            const uint32_t* Kt = Kgh + (size_t)((kt + 1) * 64) * DW;
            const uint32_t* Vt = Vgh + (size_t)((kt + 1) * 64) * DW;
            #pragma unroll
            for (int i = 0; i < 4; i++)
                kfu[i] = *(const uint4*)(Kt + (size_t)(fr + 16 * i) * DW + fc);
            #pragma unroll
            for (int i2 = 0; i2 < 2; i2++) {
                const int rp = vrp + 16 * i2;
                vau[i2] = *(const uint4*)(Vt + (size_t)(2 * rp) * DW + vds / 2);
                vbu[i2] = *(const uint4*)(Vt + (size_t)(2 * rp + 1) * DW + vds / 2);
            }
        }

        // ---- O += P @ V ----
        #pragma unroll
        for (int k16 = 0; k16 < 4; k16++) {
            uint32_t bb[8][2];
            #pragma unroll
            for (int j = 0; j < 8; j++) {
                const int w0 = (8 * j + g) * VST + 8 * k16 + tig;
                bb[j][0] = Vts[w0];
                bb[j][1] = Vts[w0 + 4];
            }
            #pragma unroll
            for (int mt = 0; mt < 2; mt++)
                #pragma unroll
                for (int j = 0; j < 8; j++)
                    mma16(of[mt][j], pa[mt][k16], bb[j]);
        }

        // ---- store next tile, single barrier ----
        if (more) {
            uint32_t* dst = sm + ((kt + 1) & 1) * STG;
            #pragma unroll
            for (int i = 0; i < 4; i++)
                *(uint4*)&dst[(fr + 16 * i) * RW + fc] = kfu[i];
            uint32_t* dstV = dst + VOFF;
            #pragma unroll
            for (int i2 = 0; i2 < 2; i2++) {
                const int rp = vrp + 16 * i2;
                const uint4 A = vau[i2], Bv = vbu[i2];
                dstV[(vds + 0) * VST + rp] = __byte_perm(A.x, Bv.x, 0x5410);
                dstV[(vds + 1) * VST + rp] = __byte_perm(A.x, Bv.x, 0x7632);
                dstV[(vds + 2) * VST + rp] = __byte_perm(A.y, Bv.y, 0x5410);
                dstV[(vds + 3) * VST + rp] = __byte_perm(A.y, Bv.y, 0x7632);
                dstV[(vds + 4) * VST + rp] = __byte_perm(A.z, Bv.z, 0x5410);
                dstV[(vds + 5) * VST + rp] = __byte_perm(A.z, Bv.z, 0x7632);
                dstV[(vds + 6) * VST + rp] = __byte_perm(A.w, Bv.w, 0x5410);
                dstV[(vds + 7) * VST + rp] = __byte_perm(A.w, Bv.w, 0x7632);
            }
        }
        __syncthreads();
    }

    // ---- normalize + write fp16 context ----
    #pragma unroll
    for (int mt = 0; mt < 2; mt++) {
        const float inv0 = 1.f / lrow[mt][0], inv1 = 1.f / lrow[mt][1];
        const size_t orow = (size_t)(b * SS + qt * 128 + wr0 + mt * 16 + g);
        #pragma unroll
        for (int j = 0; j < 8; j++) {
            const int nw = h * 32 + j * 4 + tig;   // word index (n/2)
            g_Ch[orow * DW + nw] =
                f22h(of[mt][j][0] * inv0, of[mt][j][1] * inv0);
            g_Ch[(orow + 8) * DW + nw] =
                f22h(of[mt][j][2] * inv1, of[mt][j][3] * inv1);
        }
    }
}

// ---------------------------------------------------------------------------
extern "C" void kernel_launch(void* const* d_in, const int* in_sizes, int n_in,
                              void* d_out, int out_size)
{
    (void)in_sizes; (void)n_in; (void)out_size;
    const float* q  = (const float*)d_in[0];
    const float* k  = (const float*)d_in[1];
    const float* v  = (const float*)d_in[2];
    const float* wq = (const float*)d_in[3];
    const float* bq = (const float*)d_in[4];
    const float* wk = (const float*)d_in[5];
    const float* bk = (const float*)d_in[6];
    const float* wv = (const float*)d_in[7];
    const float* bv = (const float*)d_in[8];
    const float* wo = (const float*)d_in[9];
    const float* bo = (const float*)d_in[10];
    float* out = (float*)d_out;

    uint32_t *gq, *gk, *gv, *gctx;
    cudaGetSymbolAddress((void**)&gq,   g_Qh);
    cudaGetSymbolAddress((void**)&gk,   g_Kh);
    cudaGetSymbolAddress((void**)&gv,   g_Vh);
    cudaGetSymbolAddress((void**)&gctx, g_Ch);

    cudaFuncSetAttribute(gemm_qkv, cudaFuncAttributeMaxDynamicSharedMemorySize, GEMM_SMEM);
    cudaFuncSetAttribute(gemm_out, cudaFuncAttributeMaxDynamicSharedMemorySize, GEMM_SMEM);
    cudaFuncSetAttribute(attn_tc, cudaFuncAttributeMaxDynamicSharedMemorySize, ATTN_SMEM);

    // fused Q/K/V projections (fp16 outputs; Q pre-scaled by 1/8)
    gemm_qkv<<<dim3(DD / 128, MM / 128, 3), 128, GEMM_SMEM>>>(
        q, k, v, wq, wk, wv, bq, bk, bv, gq, gk, gv);

    attn_tc<<<dim3(SS / 128, BB * HH), 128, ATTN_SMEM>>>();

    // output projection (fp16 ctx input, fp32 output)
    gemm_out<<<dim3(DD / 128, MM / 128, 1), 128, GEMM_SMEM>>>(
        gctx, wo, bo, out);
}